// round 1
// baseline (speedup 1.0000x reference)
#include <cuda_runtime.h>
#include <cuda_bf16.h>
#include <math.h>

#define SQ   2048      // sequence length S
#define EM   1024      // embed dim E
#define FF   4096      // ff dim F
#define NH   8         // heads H
#define HD   128       // head dim D
#define NL   4         // layers L
#define VC   32000     // vocab V
#define NEGV (-1.0e9f)

// ---------------- scratch (device globals; no allocation allowed) ----------
__device__ float g_h [SQ * EM];          // hidden           [S,E]
__device__ float g_hf[SQ * FF];          // relu(h@ff)       [S,F]
__device__ float g_q [SQ * NH * HD];     // q                [S,H*D]
__device__ float g_k [SQ * NH * HD];
__device__ float g_v [SQ * NH * HD];
__device__ float g_o [SQ * NH * HD];     // attn out         [S,H*D]
__device__ float g_sc[NH * SQ * SQ];     // scores/probs     [H,S,S]  (134MB)

// ---------------- embedding gather -----------------------------------------
__global__ void embed_k(const int* __restrict__ x,
                        const float* __restrict__ emb,
                        float* __restrict__ h)
{
    int s = blockIdx.x;
    int id = x[s];
    const float4* src = reinterpret_cast<const float4*>(emb + (long)id * EM);
    float4* dst = reinterpret_cast<float4*>(h + (long)s * EM);
    dst[threadIdx.x] = src[threadIdx.x];   // 256 thr * 4 = 1024 = EM
}

// ---------------- generic 128x128x16 SGEMM ---------------------------------
// MODE: 0 = plain, 1 = causal score (mask col>row with NEG, skip fully-masked
// blocks), 2 = causal-K (K loop truncated at block row end; upper-tri P == 0)
template<int TRANSB, int RELU, int MODE>
__global__ __launch_bounds__(256, 2)
void gemm_k(const float* __restrict__ Abase, const float* __restrict__ Bbase,
            float* __restrict__ Cbase,
            int M, int N, int K, int lda, int ldb, int ldc,
            long sA, long sB, long sC)
{
    const int bz = blockIdx.z;
    const float* A = Abase + (long)bz * sA;
    const float* B = Bbase + (long)bz * sB;
    float*       C = Cbase + (long)bz * sC;

    const int bm = blockIdx.y * 128;
    const int bn = blockIdx.x * 128;

    const int tid = threadIdx.x;
    const int tx = tid & 15, ty = tid >> 4;
    const int tm0 = ty * 8, tn0 = tx * 8;

    if (MODE == 1 && bn > bm + 127) {
        // entire block above the diagonal: write NEG, no compute
        const float4 nv = make_float4(NEGV, NEGV, NEGV, NEGV);
        #pragma unroll
        for (int i = 0; i < 8; i++) {
            float* crow = C + (long)(bm + tm0 + i) * ldc + bn + tn0;
            *reinterpret_cast<float4*>(crow)     = nv;
            *reinterpret_cast<float4*>(crow + 4) = nv;
        }
        return;
    }

    int Keff = K;
    if (MODE == 2) Keff = min(K, bm + 128);   // bm multiple of 128 -> mult of 16

    __shared__ float As[16][128];
    __shared__ float Bs[16][128];

    float acc[8][8];
    #pragma unroll
    for (int i = 0; i < 8; i++)
        #pragma unroll
        for (int j = 0; j < 8; j++) acc[i][j] = 0.0f;

    for (int k0 = 0; k0 < Keff; k0 += 16) {
        // ---- load A tile [128 rows x 16 k], stored transposed As[k][m]
        #pragma unroll
        for (int it = 0; it < 2; it++) {
            int f   = tid + it * 256;          // 0..511 float4s
            int k4  = (f & 3) * 4;
            int row = f >> 2;
            float4 v = *reinterpret_cast<const float4*>(
                &A[(long)(bm + row) * lda + k0 + k4]);
            As[k4 + 0][row] = v.x; As[k4 + 1][row] = v.y;
            As[k4 + 2][row] = v.z; As[k4 + 3][row] = v.w;
        }
        // ---- load B tile Bs[k][n]
        if (!TRANSB) {
            #pragma unroll
            for (int it = 0; it < 2; it++) {
                int f  = tid + it * 256;
                int n4 = (f & 31) * 4;
                int kr = f >> 5;
                *reinterpret_cast<float4*>(&Bs[kr][n4]) =
                    *reinterpret_cast<const float4*>(
                        &B[(long)(k0 + kr) * ldb + bn + n4]);
            }
        } else {
            #pragma unroll
            for (int it = 0; it < 2; it++) {
                int f  = tid + it * 256;
                int k4 = (f & 3) * 4;
                int n  = f >> 2;
                float4 v = *reinterpret_cast<const float4*>(
                    &B[(long)(bn + n) * ldb + k0 + k4]);
                Bs[k4 + 0][n] = v.x; Bs[k4 + 1][n] = v.y;
                Bs[k4 + 2][n] = v.z; Bs[k4 + 3][n] = v.w;
            }
        }
        __syncthreads();

        #pragma unroll
        for (int kk = 0; kk < 16; kk++) {
            float a[8], b[8];
            *reinterpret_cast<float4*>(&a[0]) = *reinterpret_cast<float4*>(&As[kk][tm0]);
            *reinterpret_cast<float4*>(&a[4]) = *reinterpret_cast<float4*>(&As[kk][tm0 + 4]);
            *reinterpret_cast<float4*>(&b[0]) = *reinterpret_cast<float4*>(&Bs[kk][tn0]);
            *reinterpret_cast<float4*>(&b[4]) = *reinterpret_cast<float4*>(&Bs[kk][tn0 + 4]);
            #pragma unroll
            for (int i = 0; i < 8; i++)
                #pragma unroll
                for (int j = 0; j < 8; j++)
                    acc[i][j] = fmaf(a[i], b[j], acc[i][j]);
        }
        __syncthreads();
    }

    // ---- epilogue
    #pragma unroll
    for (int i = 0; i < 8; i++) {
        int row = bm + tm0 + i;
        float* crow = C + (long)row * ldc + bn + tn0;
        #pragma unroll
        for (int jj = 0; jj < 2; jj++) {
            float r[4];
            #pragma unroll
            for (int t = 0; t < 4; t++) {
                float val = acc[i][jj * 4 + t];
                if (RELU) val = fmaxf(val, 0.0f);
                if (MODE == 1) {
                    int col = bn + tn0 + jj * 4 + t;
                    if (col > row) val = NEGV;
                }
                r[t] = val;
            }
            *reinterpret_cast<float4*>(crow + jj * 4) =
                make_float4(r[0], r[1], r[2], r[3]);
        }
    }
}

// ---------------- row softmax over S=2048 elements --------------------------
__global__ __launch_bounds__(256)
void softmax_k(float* __restrict__ scores)
{
    long row = blockIdx.x;                       // 0 .. H*S-1
    float* p = scores + row * (long)SQ;
    int tid = threadIdx.x;

    float v[8];
    float m = -INFINITY;
    #pragma unroll
    for (int i = 0; i < 8; i++) {
        v[i] = p[tid + i * 256];
        m = fmaxf(m, v[i]);
    }
    __shared__ float red[256];
    red[tid] = m; __syncthreads();
    #pragma unroll
    for (int s = 128; s > 0; s >>= 1) {
        if (tid < s) red[tid] = fmaxf(red[tid], red[tid + s]);
        __syncthreads();
    }
    m = red[0];
    __syncthreads();

    float sum = 0.0f;
    #pragma unroll
    for (int i = 0; i < 8; i++) { v[i] = __expf(v[i] - m); sum += v[i]; }
    red[tid] = sum; __syncthreads();
    #pragma unroll
    for (int s = 128; s > 0; s >>= 1) {
        if (tid < s) red[tid] += red[tid + s];
        __syncthreads();
    }
    float inv = 1.0f / red[0];
    #pragma unroll
    for (int i = 0; i < 8; i++) p[tid + i * 256] = v[i] * inv;
}

// ---------------- launch ----------------------------------------------------
extern "C" void kernel_launch(void* const* d_in, const int* in_sizes, int n_in,
                              void* d_out, int out_size)
{
    const int*   x    = (const int*)  d_in[0];  // [1,S] int32
    const float* emb  = (const float*)d_in[1];  // [V,E]
    const float* ff_w = (const float*)d_in[2];  // [L,E,F]
    const float* q_w  = (const float*)d_in[3];  // [L,F,H,D]
    const float* k_w  = (const float*)d_in[4];
    const float* v_w  = (const float*)d_in[5];
    const float* o_w  = (const float*)d_in[6];  // [L,H,D,E]
    float* out = (float*)d_out;                 // [S,V]

    float *h, *hf, *q, *k, *v, *o, *sc;
    cudaGetSymbolAddress((void**)&h,  g_h);
    cudaGetSymbolAddress((void**)&hf, g_hf);
    cudaGetSymbolAddress((void**)&q,  g_q);
    cudaGetSymbolAddress((void**)&k,  g_k);
    cudaGetSymbolAddress((void**)&v,  g_v);
    cudaGetSymbolAddress((void**)&o,  g_o);
    cudaGetSymbolAddress((void**)&sc, g_sc);

    embed_k<<<SQ, 256>>>(x, emb, h);

    const int HDALL = NH * HD;                  // 1024
    for (int l = 0; l < NL; l++) {
        // hf = relu(h @ ff_w[l]) : [S,E]x[E,F]
        gemm_k<0,1,0><<<dim3(FF/128, SQ/128, 1), 256>>>(
            h, ff_w + (long)l * EM * FF, hf,
            SQ, FF, EM, EM, FF, FF, 0, 0, 0);

        // q/k/v = hf @ w : [S,F]x[F,1024]
        gemm_k<0,0,0><<<dim3(HDALL/128, SQ/128, 1), 256>>>(
            hf, q_w + (long)l * FF * HDALL, q,
            SQ, HDALL, FF, FF, HDALL, HDALL, 0, 0, 0);
        gemm_k<0,0,0><<<dim3(HDALL/128, SQ/128, 1), 256>>>(
            hf, k_w + (long)l * FF * HDALL, k,
            SQ, HDALL, FF, FF, HDALL, HDALL, 0, 0, 0);
        gemm_k<0,0,0><<<dim3(HDALL/128, SQ/128, 1), 256>>>(
            hf, v_w + (long)l * FF * HDALL, v,
            SQ, HDALL, FF, FF, HDALL, HDALL, 0, 0, 0);

        // scores[h] = q_h @ k_h^T  (causal mask), per-head batch in z
        gemm_k<1,0,1><<<dim3(SQ/128, SQ/128, NH), 256>>>(
            q, k, sc,
            SQ, SQ, HD, HDALL, HDALL, SQ,
            (long)HD, (long)HD, (long)SQ * SQ);

        // softmax rows
        softmax_k<<<NH * SQ, 256>>>(sc);

        // o[h] = P_h @ v_h : [S,S]x[S,D], K truncated by causality
        gemm_k<0,0,2><<<dim3(HD/128, SQ/128, NH), 256>>>(
            sc, v, o,
            SQ, HD, SQ, SQ, HDALL, HDALL,
            (long)SQ * SQ, (long)HD, (long)HD);

        // h = o @ o_w[l] : [S,1024]x[1024,E]
        gemm_k<0,0,0><<<dim3(EM/128, SQ/128, 1), 256>>>(
            o, o_w + (long)l * HDALL * EM, h,
            SQ, EM, HDALL, HDALL, EM, EM, 0, 0, 0);
    }

    // logits = h @ emb^T : [S,E]x[V,E]^T
    gemm_k<1,0,0><<<dim3(VC/128, SQ/128, 1), 256>>>(
        h, emb, out,
        SQ, VC, EM, EM, EM, VC, 0, 0, 0);
}

// round 6
// speedup vs baseline: 2.8250x; 2.8250x over previous
#include <cuda_runtime.h>
#include <cuda_bf16.h>
#include <math.h>
#include <stdint.h>

#define SQ   2048
#define EM   1024
#define FF   4096
#define NH   8
#define HD   128
#define NL   4
#define VC   32000
#define NEGV (-1.0e9f)

// ---------------- scratch (device globals) ----------------------------------
__device__ float g_h [SQ * EM];
__device__ float g_hf[SQ * FF];
__device__ float g_q [SQ * NH * HD];
__device__ float g_k [SQ * NH * HD];
__device__ float g_v [SQ * NH * HD];
__device__ float g_o [SQ * NH * HD];
__device__ float g_sc[NH * SQ * SQ];

// ---------------- helpers ----------------------------------------------------
__device__ __forceinline__ uint32_t f2tf(float f) {
    uint32_t r;
    asm("cvt.rna.tf32.f32 %0, %1;" : "=r"(r) : "f"(f));
    return r;
}
__device__ __forceinline__ void cp16(uint32_t dst, const float* src) {
    asm volatile("cp.async.cg.shared.global [%0], [%1], 16;"
                 :: "r"(dst), "l"(src) : "memory");
}
#define CP_COMMIT() asm volatile("cp.async.commit_group;" ::: "memory")
#define CP_WAIT0()  asm volatile("cp.async.wait_group 0;" ::: "memory")
#define CP_WAIT1()  asm volatile("cp.async.wait_group 1;" ::: "memory")

#define MMA_TF32(d, a, b) \
    asm volatile("mma.sync.aligned.m16n8k8.row.col.f32.tf32.tf32.f32 " \
                 "{%0,%1,%2,%3},{%4,%5,%6,%7},{%8,%9},{%0,%1,%2,%3};" \
                 : "+f"((d)[0]), "+f"((d)[1]), "+f"((d)[2]), "+f"((d)[3]) \
                 : "r"((a)[0]), "r"((a)[1]), "r"((a)[2]), "r"((a)[3]), \
                   "r"((b)[0]), "r"((b)[1]))

// ---------------- embedding gather ------------------------------------------
__global__ void embed_k(const int* __restrict__ x, const float* __restrict__ emb,
                        float* __restrict__ h)
{
    int s = blockIdx.x;
    int id = x[s];
    const float4* src = reinterpret_cast<const float4*>(emb + (long)id * EM);
    float4* dst = reinterpret_cast<float4*>(h + (long)s * EM);
    dst[threadIdx.x] = src[threadIdx.x];
}

// ---------------- tf32 mma.sync GEMM: 128x128 tile, BK=32 -------------------
// TRANSB: 1 = B stored [N,K] (K contiguous), 0 = B stored [K,N] (N contiguous)
// MODE:   0 plain, 1 causal scores (skip bn>bm tiles, mask diagonal),
//         2 causal-K truncation (K loop stops at block-row end)
//
// SMEM layout per buffer slot (4608 floats = 18432 B):
//   A  : [128 rows][stride 36]  (row-major, k contiguous)   -> frag bank-free
//   B,TRANSB=1: [128 n][stride 36]                           -> frag bank-free
//   B,TRANSB=0: [32 k][stride 136]                           -> frag bank-free
template<int TRANSB, int RELU, int MODE>
__global__ __launch_bounds__(256, 2)
void mgemm_k(const float* __restrict__ Abase, const float* __restrict__ Bbase,
             float* __restrict__ Cbase, int M, int N, int K,
             int lda, int ldb, int ldc, long sA, long sB, long sC)
{
    const int bz = blockIdx.z;
    const float* A = Abase + (long)bz * sA;
    const float* B = Bbase + (long)bz * sB;
    float*       C = Cbase + (long)bz * sC;
    const int bm = blockIdx.y * 128;
    const int bn = blockIdx.x * 128;
    const int tid = threadIdx.x;
    const int wid = tid >> 5, lane = tid & 31;
    const int g = lane >> 2, tg = lane & 3;      // group / thread-in-group
    const int wm = wid >> 2, wn = wid & 3;       // warp grid 2 x 4

    if (MODE == 1 && bn > bm) {                  // fully masked tile: NEG fill
        const float4 nv = make_float4(NEGV, NEGV, NEGV, NEGV);
        for (int i = tid; i < 4096; i += 256) {
            int row = i >> 5, c4 = (i & 31) * 4;
            *reinterpret_cast<float4*>(C + (long)(bm + row) * ldc + bn + c4) = nv;
        }
        return;
    }

    extern __shared__ float smem[];
    float* Asp[2] = { smem,            smem + 9216  };
    float* Bsp[2] = { smem + 4608,     smem + 13824 };
    const uint32_t asu[2] = { (uint32_t)__cvta_generic_to_shared(Asp[0]),
                              (uint32_t)__cvta_generic_to_shared(Asp[1]) };
    const uint32_t bsu[2] = { (uint32_t)__cvta_generic_to_shared(Bsp[0]),
                              (uint32_t)__cvta_generic_to_shared(Bsp[1]) };

    const int Keff = (MODE == 2) ? min(K, bm + 128) : K;
    const int T = Keff >> 5;

    float acc[4][4][4];
    #pragma unroll
    for (int mi = 0; mi < 4; mi++)
        #pragma unroll
        for (int ni = 0; ni < 4; ni++)
            #pragma unroll
            for (int e = 0; e < 4; e++) acc[mi][ni][e] = 0.0f;

    auto load_tile = [&](int t, int buf) {
        const int k0 = t * 32;
        #pragma unroll
        for (int i = 0; i < 4; i++) {            // A: 1024 16B chunks / 256 thr
            int f = tid + i * 256;
            int row = f >> 3, c = f & 7;
            cp16(asu[buf] + (uint32_t)(row * 36 + c * 4) * 4u,
                 A + (long)(bm + row) * lda + k0 + c * 4);
        }
        if (TRANSB) {
            #pragma unroll
            for (int i = 0; i < 4; i++) {
                int f = tid + i * 256;
                int row = f >> 3, c = f & 7;
                cp16(bsu[buf] + (uint32_t)(row * 36 + c * 4) * 4u,
                     B + (long)(bn + row) * ldb + k0 + c * 4);
            }
        } else {
            #pragma unroll
            for (int i = 0; i < 4; i++) {
                int f = tid + i * 256;
                int kr = f >> 5, c = f & 31;
                cp16(bsu[buf] + (uint32_t)(kr * 136 + c * 4) * 4u,
                     B + (long)(k0 + kr) * ldb + bn + c * 4);
            }
        }
        CP_COMMIT();
    };

    auto compute = [&](int buf) {
        const float* as = Asp[buf];
        const float* bs = Bsp[buf];
        #pragma unroll
        for (int ks = 0; ks < 4; ks++) {
            const int kk = ks * 8;
            uint32_t af[4][4];
            #pragma unroll
            for (int mi = 0; mi < 4; mi++) {
                int r = wm * 64 + mi * 16 + g;
                af[mi][0] = f2tf(as[r * 36 + kk + tg]);
                af[mi][1] = f2tf(as[(r + 8) * 36 + kk + tg]);
                af[mi][2] = f2tf(as[r * 36 + kk + tg + 4]);
                af[mi][3] = f2tf(as[(r + 8) * 36 + kk + tg + 4]);
            }
            uint32_t bf[4][2];
            #pragma unroll
            for (int ni = 0; ni < 4; ni++) {
                int n = wn * 32 + ni * 8 + g;
                if (TRANSB) {
                    bf[ni][0] = f2tf(bs[n * 36 + kk + tg]);
                    bf[ni][1] = f2tf(bs[n * 36 + kk + tg + 4]);
                } else {
                    bf[ni][0] = f2tf(bs[(kk + tg) * 136 + n]);
                    bf[ni][1] = f2tf(bs[(kk + tg + 4) * 136 + n]);
                }
            }
            #pragma unroll
            for (int mi = 0; mi < 4; mi++)
                #pragma unroll
                for (int ni = 0; ni < 4; ni++)
                    MMA_TF32(acc[mi][ni], af[mi], bf[ni]);
        }
    };

    load_tile(0, 0);
    for (int t = 0; t < T; t++) {
        if (t + 1 < T) { load_tile(t + 1, (t + 1) & 1); CP_WAIT1(); }
        else           { CP_WAIT0(); }
        __syncthreads();
        compute(t & 1);
        __syncthreads();
    }

    // ---- epilogue: write acc to C with RELU / causal mask -------------------
    #pragma unroll
    for (int mi = 0; mi < 4; mi++) {
        int r0 = bm + wm * 64 + mi * 16 + g;
        #pragma unroll
        for (int ni = 0; ni < 4; ni++) {
            int c0 = bn + wn * 32 + ni * 8 + 2 * tg;
            float e0 = acc[mi][ni][0], e1 = acc[mi][ni][1];
            float e2 = acc[mi][ni][2], e3 = acc[mi][ni][3];
            if (RELU) {
                e0 = fmaxf(e0, 0.f); e1 = fmaxf(e1, 0.f);
                e2 = fmaxf(e2, 0.f); e3 = fmaxf(e3, 0.f);
            }
            if (MODE == 1 && bn == bm) {
                if (c0     > r0)     e0 = NEGV;
                if (c0 + 1 > r0)     e1 = NEGV;
                if (c0     > r0 + 8) e2 = NEGV;
                if (c0 + 1 > r0 + 8) e3 = NEGV;
            }
            *reinterpret_cast<float2*>(C + (long)r0 * ldc + c0) =
                make_float2(e0, e1);
            *reinterpret_cast<float2*>(C + (long)(r0 + 8) * ldc + c0) =
                make_float2(e2, e3);
        }
    }
}

// ---------------- row softmax ------------------------------------------------
__global__ __launch_bounds__(256)
void softmax_k(float* __restrict__ scores)
{
    long row = blockIdx.x;
    float* p = scores + row * (long)SQ;
    int tid = threadIdx.x;

    float v[8];
    float m = -INFINITY;
    #pragma unroll
    for (int i = 0; i < 8; i++) { v[i] = p[tid + i * 256]; m = fmaxf(m, v[i]); }
    __shared__ float red[256];
    red[tid] = m; __syncthreads();
    #pragma unroll
    for (int s = 128; s > 0; s >>= 1) {
        if (tid < s) red[tid] = fmaxf(red[tid], red[tid + s]);
        __syncthreads();
    }
    m = red[0];
    __syncthreads();
    float sum = 0.0f;
    #pragma unroll
    for (int i = 0; i < 8; i++) { v[i] = __expf(v[i] - m); sum += v[i]; }
    red[tid] = sum; __syncthreads();
    #pragma unroll
    for (int s = 128; s > 0; s >>= 1) {
        if (tid < s) red[tid] += red[tid + s];
        __syncthreads();
    }
    float inv = 1.0f / red[0];
    #pragma unroll
    for (int i = 0; i < 8; i++) p[tid + i * 256] = v[i] * inv;
}

// ---------------- launch -----------------------------------------------------
#define SMEM_DYN (4 * 4608 * 4)   // 73728 B: 2 x (A 18432 + B 18432)

extern "C" void kernel_launch(void* const* d_in, const int* in_sizes, int n_in,
                              void* d_out, int out_size)
{
    const int*   x    = (const int*)  d_in[0];
    const float* emb  = (const float*)d_in[1];
    const float* ff_w = (const float*)d_in[2];
    const float* q_w  = (const float*)d_in[3];
    const float* k_w  = (const float*)d_in[4];
    const float* v_w  = (const float*)d_in[5];
    const float* o_w  = (const float*)d_in[6];
    float* out = (float*)d_out;

    float *h, *hf, *q, *k, *v, *o, *sc;
    cudaGetSymbolAddress((void**)&h,  g_h);
    cudaGetSymbolAddress((void**)&hf, g_hf);
    cudaGetSymbolAddress((void**)&q,  g_q);
    cudaGetSymbolAddress((void**)&k,  g_k);
    cudaGetSymbolAddress((void**)&v,  g_v);
    cudaGetSymbolAddress((void**)&o,  g_o);
    cudaGetSymbolAddress((void**)&sc, g_sc);

    cudaFuncSetAttribute(mgemm_k<0,1,0>, cudaFuncAttributeMaxDynamicSharedMemorySize, SMEM_DYN);
    cudaFuncSetAttribute(mgemm_k<0,0,0>, cudaFuncAttributeMaxDynamicSharedMemorySize, SMEM_DYN);
    cudaFuncSetAttribute(mgemm_k<1,0,1>, cudaFuncAttributeMaxDynamicSharedMemorySize, SMEM_DYN);
    cudaFuncSetAttribute(mgemm_k<0,0,2>, cudaFuncAttributeMaxDynamicSharedMemorySize, SMEM_DYN);
    cudaFuncSetAttribute(mgemm_k<1,0,0>, cudaFuncAttributeMaxDynamicSharedMemorySize, SMEM_DYN);

    embed_k<<<SQ, 256>>>(x, emb, h);

    const int HDALL = NH * HD;                  // 1024
    for (int l = 0; l < NL; l++) {
        // hf = relu(h @ ff_w[l]) : [S,E]x[E,F]
        mgemm_k<0,1,0><<<dim3(FF/128, SQ/128, 1), 256, SMEM_DYN>>>(
            h, ff_w + (long)l * EM * FF, hf,
            SQ, FF, EM, EM, FF, FF, 0, 0, 0);

        // q/k/v = hf @ w : [S,F]x[F,1024]
        mgemm_k<0,0,0><<<dim3(HDALL/128, SQ/128, 1), 256, SMEM_DYN>>>(
            hf, q_w + (long)l * FF * HDALL, q,
            SQ, HDALL, FF, FF, HDALL, HDALL, 0, 0, 0);
        mgemm_k<0,0,0><<<dim3(HDALL/128, SQ/128, 1), 256, SMEM_DYN>>>(
            hf, k_w + (long)l * FF * HDALL, k,
            SQ, HDALL, FF, FF, HDALL, HDALL, 0, 0, 0);
        mgemm_k<0,0,0><<<dim3(HDALL/128, SQ/128, 1), 256, SMEM_DYN>>>(
            hf, v_w + (long)l * FF * HDALL, v,
            SQ, HDALL, FF, FF, HDALL, HDALL, 0, 0, 0);

        // scores[h] = q_h @ k_h^T (causal), batched over heads in z
        mgemm_k<1,0,1><<<dim3(SQ/128, SQ/128, NH), 256, SMEM_DYN>>>(
            q, k, sc,
            SQ, SQ, HD, HDALL, HDALL, SQ,
            (long)HD, (long)HD, (long)SQ * SQ);

        softmax_k<<<NH * SQ, 256>>>(sc);

        // o[h] = P_h @ v_h, K truncated by causality
        mgemm_k<0,0,2><<<dim3(HD/128, SQ/128, NH), 256, SMEM_DYN>>>(
            sc, v, o,
            SQ, HD, SQ, SQ, HDALL, HDALL,
            (long)SQ * SQ, (long)HD, (long)HD);

        // h = o @ o_w[l]
        mgemm_k<0,0,0><<<dim3(EM/128, SQ/128, 1), 256, SMEM_DYN>>>(
            o, o_w + (long)l * HDALL * EM, h,
            SQ, EM, HDALL, HDALL, EM, EM, 0, 0, 0);
    }

    // logits = h @ emb^T
    mgemm_k<1,0,0><<<dim3(VC/128, SQ/128, 1), 256, SMEM_DYN>>>(
        h, emb, out,
        SQ, VC, EM, EM, EM, VC, 0, 0, 0);
}

// round 8
// speedup vs baseline: 2.8689x; 1.0155x over previous
#include <cuda_runtime.h>
#include <cuda_bf16.h>
#include <math.h>
#include <stdint.h>

#define SQ   2048
#define EM   1024
#define FF   4096
#define NH   8
#define HD   128
#define NL   4
#define VC   32000
#define NEGV (-1.0e9f)

// ---------------- scratch (device globals) ----------------------------------
__device__ float g_h [SQ * EM];
__device__ float g_hf[SQ * FF];
__device__ float g_q [SQ * NH * HD];
__device__ float g_k [SQ * NH * HD];
__device__ float g_v [SQ * NH * HD];
__device__ float g_o [SQ * NH * HD];
__device__ float g_sc[NH * SQ * SQ];

// ---------------- helpers ----------------------------------------------------
__device__ __forceinline__ uint32_t f2tf(float f) {
    uint32_t r;
    asm("cvt.rna.tf32.f32 %0, %1;" : "=r"(r) : "f"(f));
    return r;
}
__device__ __forceinline__ float roundtf(float f) {
    return __uint_as_float(f2tf(f));
}
__device__ __forceinline__ void cp16(uint32_t dst, const float* src) {
    asm volatile("cp.async.cg.shared.global [%0], [%1], 16;"
                 :: "r"(dst), "l"(src) : "memory");
}
#define CP_COMMIT() asm volatile("cp.async.commit_group;" ::: "memory")
#define CP_WAIT0()  asm volatile("cp.async.wait_group 0;" ::: "memory")
#define CP_WAIT1()  asm volatile("cp.async.wait_group 1;" ::: "memory")

#define MMA_TF32(d, a, b) \
    asm volatile("mma.sync.aligned.m16n8k8.row.col.f32.tf32.tf32.f32 " \
                 "{%0,%1,%2,%3},{%4,%5,%6,%7},{%8,%9},{%0,%1,%2,%3};" \
                 : "+f"((d)[0]), "+f"((d)[1]), "+f"((d)[2]), "+f"((d)[3]) \
                 : "r"((a)[0]), "r"((a)[1]), "r"((a)[2]), "r"((a)[3]), \
                   "r"((b)[0]), "r"((b)[1]))

// ---------------- embedding gather (rounds to tf32) --------------------------
__global__ void embed_k(const int* __restrict__ x, const float* __restrict__ emb,
                        float* __restrict__ h)
{
    int s = blockIdx.x;
    int id = x[s];
    const float4* src = reinterpret_cast<const float4*>(emb + (long)id * EM);
    float4 v = src[threadIdx.x];
    v.x = roundtf(v.x); v.y = roundtf(v.y);
    v.z = roundtf(v.z); v.w = roundtf(v.w);
    reinterpret_cast<float4*>(h + (long)s * EM)[threadIdx.x] = v;
}

// ---------------- tf32 mma.sync GEMM: 128 x TILEN tile, BK=32 ----------------
// TILEN : 128 (warp grid 2x4, 64x32/warp) or 64 (warp grid 4x2, 32x32/warp)
// TRANSB: 1 = B stored [N,K] (K contiguous), 0 = B stored [K,N]
// CVTB  : 1 = B fragments need cvt.rna.tf32 (raw weights); 0 = pre-rounded
// ROUNDC: 1 = round C to tf32 on store (activation outputs)
// MODE  : 0 plain, 1 causal scores, 2 causal-K truncation
template<int TILEN, int TRANSB, int CVTB, int RELU, int ROUNDC, int MODE>
__global__ __launch_bounds__(256, 2)
void mgemm_k(const float* __restrict__ Abase, const float* __restrict__ Bbase,
             float* __restrict__ Cbase, int M, int N, int K,
             int lda, int ldb, int ldc, long sA, long sB, long sC)
{
    constexpr int BN    = TILEN;
    constexpr int MI    = (TILEN == 128) ? 4 : 2;   // m16 tiles per warp
    constexpr int BBUF  = (TILEN == 128) ? 4608 : 2304;  // floats
    constexpr int BUFSZ = 4608 + BBUF;
    constexpr int BSTR_N = (TILEN == 128) ? 136 : 72;    // [K,N] layout stride
    constexpr int NCH    = BN / 4;                        // 16B chunks per k-row
    constexpr int BITERS = (TILEN == 128) ? 4 : 2;

    const int bz = blockIdx.z;
    const float* A = Abase + (long)bz * sA;
    const float* B = Bbase + (long)bz * sB;
    float*       C = Cbase + (long)bz * sC;
    const int bm = blockIdx.y * 128;
    const int bn = blockIdx.x * BN;
    const int tid = threadIdx.x;
    const int wid = tid >> 5, lane = tid & 31;
    const int g = lane >> 2, tg = lane & 3;
    const int wm = (TILEN == 128) ? (wid >> 2) : (wid >> 1);
    const int wn = (TILEN == 128) ? (wid & 3)  : (wid & 1);
    const int moff = wm * ((TILEN == 128) ? 64 : 32);

    if (MODE == 1 && bn > bm) {                  // fully masked tile: NEG fill
        const float4 nv = make_float4(NEGV, NEGV, NEGV, NEGV);
        for (int i = tid; i < 128 * BN / 4; i += 256) {
            int row = i / (BN / 4), c4 = (i % (BN / 4)) * 4;
            *reinterpret_cast<float4*>(C + (long)(bm + row) * ldc + bn + c4) = nv;
        }
        return;
    }

    extern __shared__ float smem[];
    float* Asp[2] = { smem,         smem + BUFSZ };
    float* Bsp[2] = { smem + 4608,  smem + BUFSZ + 4608 };
    const uint32_t asu[2] = { (uint32_t)__cvta_generic_to_shared(Asp[0]),
                              (uint32_t)__cvta_generic_to_shared(Asp[1]) };
    const uint32_t bsu[2] = { (uint32_t)__cvta_generic_to_shared(Bsp[0]),
                              (uint32_t)__cvta_generic_to_shared(Bsp[1]) };

    const int Keff = (MODE == 2) ? min(K, bm + 128) : K;
    const int T = Keff >> 5;

    float acc[MI][4][4];
    #pragma unroll
    for (int mi = 0; mi < MI; mi++)
        #pragma unroll
        for (int ni = 0; ni < 4; ni++)
            #pragma unroll
            for (int e = 0; e < 4; e++) acc[mi][ni][e] = 0.0f;

    auto load_tile = [&](int t, int buf) {
        const int k0 = t * 32;
        #pragma unroll
        for (int i = 0; i < 4; i++) {            // A: 1024 16B chunks
            int f = tid + i * 256;
            int row = f >> 3, c = f & 7;
            cp16(asu[buf] + (uint32_t)(row * 36 + c * 4) * 4u,
                 A + (long)(bm + row) * lda + k0 + c * 4);
        }
        #pragma unroll
        for (int i = 0; i < BITERS; i++) {
            int f = tid + i * 256;
            if (TRANSB) {                        // [N,K] rows, k contiguous
                int row = f >> 3, c = f & 7;
                cp16(bsu[buf] + (uint32_t)(row * 36 + c * 4) * 4u,
                     B + (long)(bn + row) * ldb + k0 + c * 4);
            } else {                             // [K,N] rows, n contiguous
                int kr = f / NCH, c = f % NCH;
                cp16(bsu[buf] + (uint32_t)(kr * BSTR_N + c * 4) * 4u,
                     B + (long)(k0 + kr) * ldb + bn + c * 4);
            }
        }
        CP_COMMIT();
    };

    auto compute = [&](int buf) {
        const float* as = Asp[buf];
        const float* bs = Bsp[buf];
        #pragma unroll
        for (int ks = 0; ks < 4; ks++) {
            const int kk = ks * 8;
            uint32_t af[MI][4];
            #pragma unroll
            for (int mi = 0; mi < MI; mi++) {
                int r = moff + mi * 16 + g;
                af[mi][0] = __float_as_uint(as[r * 36 + kk + tg]);
                af[mi][1] = __float_as_uint(as[(r + 8) * 36 + kk + tg]);
                af[mi][2] = __float_as_uint(as[r * 36 + kk + tg + 4]);
                af[mi][3] = __float_as_uint(as[(r + 8) * 36 + kk + tg + 4]);
            }
            uint32_t bf[4][2];
            #pragma unroll
            for (int ni = 0; ni < 4; ni++) {
                int n = wn * 32 + ni * 8 + g;
                float r0 = TRANSB ? bs[n * 36 + kk + tg]
                                  : bs[(kk + tg) * BSTR_N + n];
                float r1 = TRANSB ? bs[n * 36 + kk + tg + 4]
                                  : bs[(kk + tg + 4) * BSTR_N + n];
                bf[ni][0] = CVTB ? f2tf(r0) : __float_as_uint(r0);
                bf[ni][1] = CVTB ? f2tf(r1) : __float_as_uint(r1);
            }
            #pragma unroll
            for (int mi = 0; mi < MI; mi++)
                #pragma unroll
                for (int ni = 0; ni < 4; ni++)
                    MMA_TF32(acc[mi][ni], af[mi], bf[ni]);
        }
    };

    load_tile(0, 0);
    for (int t = 0; t < T; t++) {
        if (t + 1 < T) { load_tile(t + 1, (t + 1) & 1); CP_WAIT1(); }
        else           { CP_WAIT0(); }
        __syncthreads();
        compute(t & 1);
        __syncthreads();
    }

    // ---- epilogue -----------------------------------------------------------
    #pragma unroll
    for (int mi = 0; mi < MI; mi++) {
        int r0 = bm + moff + mi * 16 + g;
        #pragma unroll
        for (int ni = 0; ni < 4; ni++) {
            int c0 = bn + wn * 32 + ni * 8 + 2 * tg;
            float e0 = acc[mi][ni][0], e1 = acc[mi][ni][1];
            float e2 = acc[mi][ni][2], e3 = acc[mi][ni][3];
            if (RELU) {
                e0 = fmaxf(e0, 0.f); e1 = fmaxf(e1, 0.f);
                e2 = fmaxf(e2, 0.f); e3 = fmaxf(e3, 0.f);
            }
            if (MODE == 1 && bn == bm) {
                if (c0     > r0)     e0 = NEGV;
                if (c0 + 1 > r0)     e1 = NEGV;
                if (c0     > r0 + 8) e2 = NEGV;
                if (c0 + 1 > r0 + 8) e3 = NEGV;
            }
            if (ROUNDC) {
                e0 = roundtf(e0); e1 = roundtf(e1);
                e2 = roundtf(e2); e3 = roundtf(e3);
            }
            *reinterpret_cast<float2*>(C + (long)r0 * ldc + c0) =
                make_float2(e0, e1);
            *reinterpret_cast<float2*>(C + (long)(r0 + 8) * ldc + c0) =
                make_float2(e2, e3);
        }
    }
}

// ---------------- row softmax (stores tf32-rounded probs) --------------------
__global__ __launch_bounds__(256)
void softmax_k(float* __restrict__ scores)
{
    long row = blockIdx.x;
    float* p = scores + row * (long)SQ;
    int tid = threadIdx.x;

    float v[8];
    float m = -INFINITY;
    #pragma unroll
    for (int i = 0; i < 8; i++) { v[i] = p[tid + i * 256]; m = fmaxf(m, v[i]); }
    __shared__ float red[256];
    red[tid] = m; __syncthreads();
    #pragma unroll
    for (int s = 128; s > 0; s >>= 1) {
        if (tid < s) red[tid] = fmaxf(red[tid], red[tid + s]);
        __syncthreads();
    }
    m = red[0];
    __syncthreads();
    float sum = 0.0f;
    #pragma unroll
    for (int i = 0; i < 8; i++) { v[i] = __expf(v[i] - m); sum += v[i]; }
    red[tid] = sum; __syncthreads();
    #pragma unroll
    for (int s = 128; s > 0; s >>= 1) {
        if (tid < s) red[tid] += red[tid + s];
        __syncthreads();
    }
    float inv = 1.0f / red[0];
    #pragma unroll
    for (int i = 0; i < 8; i++) p[tid + i * 256] = roundtf(v[i] * inv);
}

// ---------------- launch -----------------------------------------------------
#define SM128 73728     // 2 * (4608 + 4608) * 4
#define SM64  55296     // 2 * (4608 + 2304) * 4

extern "C" void kernel_launch(void* const* d_in, const int* in_sizes, int n_in,
                              void* d_out, int out_size)
{
    const int*   x    = (const int*)  d_in[0];
    const float* emb  = (const float*)d_in[1];
    const float* ff_w = (const float*)d_in[2];
    const float* q_w  = (const float*)d_in[3];
    const float* k_w  = (const float*)d_in[4];
    const float* v_w  = (const float*)d_in[5];
    const float* o_w  = (const float*)d_in[6];
    float* out = (float*)d_out;

    float *h, *hf, *q, *k, *v, *o, *sc;
    cudaGetSymbolAddress((void**)&h,  g_h);
    cudaGetSymbolAddress((void**)&hf, g_hf);
    cudaGetSymbolAddress((void**)&q,  g_q);
    cudaGetSymbolAddress((void**)&k,  g_k);
    cudaGetSymbolAddress((void**)&v,  g_v);
    cudaGetSymbolAddress((void**)&o,  g_o);
    cudaGetSymbolAddress((void**)&sc, g_sc);

    // FF: TILEN=128, weights (CVTB), relu, round out
    cudaFuncSetAttribute(mgemm_k<128,0,1,1,1,0>, cudaFuncAttributeMaxDynamicSharedMemorySize, SM128);
    // QKV / O-proj: TILEN=64, weights, round out
    cudaFuncSetAttribute(mgemm_k<64,0,1,0,1,0>,  cudaFuncAttributeMaxDynamicSharedMemorySize, SM64);
    // scores: TILEN=128, TRANSB, no cvt, no round (fp32 into softmax)
    cudaFuncSetAttribute(mgemm_k<128,1,0,0,0,1>, cudaFuncAttributeMaxDynamicSharedMemorySize, SM128);
    // PV: TILEN=64, no cvt, round out, causal-K
    cudaFuncSetAttribute(mgemm_k<64,0,0,0,1,2>,  cudaFuncAttributeMaxDynamicSharedMemorySize, SM64);
    // logits: TILEN=128, TRANSB, emb needs cvt, raw fp32 out
    cudaFuncSetAttribute(mgemm_k<128,1,1,0,0,0>, cudaFuncAttributeMaxDynamicSharedMemorySize, SM128);

    embed_k<<<SQ, 256>>>(x, emb, h);

    const int HDALL = NH * HD;                  // 1024
    for (int l = 0; l < NL; l++) {
        // hf = relu(h @ ff_w[l]) : [S,E]x[E,F]
        mgemm_k<128,0,1,1,1,0><<<dim3(FF/128, SQ/128, 1), 256, SM128>>>(
            h, ff_w + (long)l * EM * FF, hf,
            SQ, FF, EM, EM, FF, FF, 0, 0, 0);

        // q/k/v = hf @ w : [S,F]x[F,1024], TILEN=64 -> 256 CTAs
        mgemm_k<64,0,1,0,1,0><<<dim3(HDALL/64, SQ/128, 1), 256, SM64>>>(
            hf, q_w + (long)l * FF * HDALL, q,
            SQ, HDALL, FF, FF, HDALL, HDALL, 0, 0, 0);
        mgemm_k<64,0,1,0,1,0><<<dim3(HDALL/64, SQ/128, 1), 256, SM64>>>(
            hf, k_w + (long)l * FF * HDALL, k,
            SQ, HDALL, FF, FF, HDALL, HDALL, 0, 0, 0);
        mgemm_k<64,0,1,0,1,0><<<dim3(HDALL/64, SQ/128, 1), 256, SM64>>>(
            hf, v_w + (long)l * FF * HDALL, v,
            SQ, HDALL, FF, FF, HDALL, HDALL, 0, 0, 0);

        // scores[h] = q_h @ k_h^T (causal), batched over heads in z
        mgemm_k<128,1,0,0,0,1><<<dim3(SQ/128, SQ/128, NH), 256, SM128>>>(
            q, k, sc,
            SQ, SQ, HD, HDALL, HDALL, SQ,
            (long)HD, (long)HD, (long)SQ * SQ);

        softmax_k<<<NH * SQ, 256>>>(sc);

        // o[h] = P_h @ v_h, K truncated by causality, TILEN=64 -> 256 CTAs
        mgemm_k<64,0,0,0,1,2><<<dim3(HD/64, SQ/128, NH), 256, SM64>>>(
            sc, v, o,
            SQ, HD, SQ, SQ, HDALL, HDALL,
            (long)SQ * SQ, (long)HD, (long)HD);

        // h = o @ o_w[l], TILEN=64 -> 256 CTAs
        mgemm_k<64,0,1,0,1,0><<<dim3(EM/64, SQ/128, 1), 256, SM64>>>(
            o, o_w + (long)l * HDALL * EM, h,
            SQ, EM, HDALL, HDALL, EM, EM, 0, 0, 0);
    }

    // logits = h @ emb^T
    mgemm_k<128,1,1,0,0,0><<<dim3(VC/128, SQ/128, 1), 256, SM128>>>(
        h, emb, out,
        SQ, VC, EM, EM, EM, VC, 0, 0, 0);
}

// round 11
// speedup vs baseline: 3.7961x; 1.3232x over previous
#include <cuda_runtime.h>
#include <cuda_bf16.h>
#include <math.h>
#include <stdint.h>

#define SQ   2048
#define EM   1024
#define FF   4096
#define NH   8
#define HD   128
#define NL   4
#define VC   32000
#define NEGV (-1.0e9f)
#define HDALL (NH * HD)

// ---------------- scratch (device globals) ----------------------------------
__device__ float g_h [SQ * EM];
__device__ float g_hf[SQ * FF];
__device__ float g_q [SQ * NH * HD];
__device__ float g_k [SQ * NH * HD];
__device__ float g_v [SQ * NH * HD];
__device__ float g_o [SQ * NH * HD];
__device__ float g_sc[NH * SQ * SQ];

// ---------------- helpers ----------------------------------------------------
__device__ __forceinline__ uint32_t f2tf(float f) {
    uint32_t r;
    asm("cvt.rna.tf32.f32 %0, %1;" : "=r"(r) : "f"(f));
    return r;
}
__device__ __forceinline__ float roundtf(float f) {
    return __uint_as_float(f2tf(f));
}
__device__ __forceinline__ void cp16(uint32_t dst, const float* src) {
    asm volatile("cp.async.cg.shared.global [%0], [%1], 16;"
                 :: "r"(dst), "l"(src) : "memory");
}
#define CP_COMMIT() asm volatile("cp.async.commit_group;" ::: "memory")
#define CP_WAIT0()  asm volatile("cp.async.wait_group 0;" ::: "memory")
#define CP_WAIT1()  asm volatile("cp.async.wait_group 1;" ::: "memory")

#define MMA_TF32(d, a, b) \
    asm volatile("mma.sync.aligned.m16n8k8.row.col.f32.tf32.tf32.f32 " \
                 "{%0,%1,%2,%3},{%4,%5,%6,%7},{%8,%9},{%0,%1,%2,%3};" \
                 : "+f"((d)[0]), "+f"((d)[1]), "+f"((d)[2]), "+f"((d)[3]) \
                 : "r"((a)[0]), "r"((a)[1]), "r"((a)[2]), "r"((a)[3]), \
                   "r"((b)[0]), "r"((b)[1]))

// ---------------- embedding gather (rounds to tf32) --------------------------
__global__ void embed_k(const int* __restrict__ x, const float* __restrict__ emb,
                        float* __restrict__ h)
{
    int s = blockIdx.x;
    int id = x[s];
    const float4* src = reinterpret_cast<const float4*>(emb + (long)id * EM);
    float4 v = src[threadIdx.x];
    v.x = roundtf(v.x); v.y = roundtf(v.y);
    v.z = roundtf(v.z); v.w = roundtf(v.w);
    reinterpret_cast<float4*>(h + (long)s * EM)[threadIdx.x] = v;
}

// ---------------- GEMM body: 128 x TILEN tile, BK=32, 3-stage pipeline ------
// TILEN : 128 (warps 2x4, 64x32 each) or 64 (warps 4x2, 32x32 each)
// TRANSB: 1 = B stored [N,K] (K contiguous), 0 = B stored [K,N]
// CVTB  : 1 = B fragments need cvt.rna.tf32; 0 = pre-rounded activations
// ROUNDC: 1 = round C to tf32 on store
// MODE  : 0 plain, 1 causal-diag mask (bm==bn tile), 2 causal-K truncation
template<int TILEN, int TRANSB, int CVTB, int RELU, int ROUNDC, int MODE>
__device__ __forceinline__
void gemm_body(const float* __restrict__ A, const float* __restrict__ B,
               float* __restrict__ C, int K, int lda, int ldb, int ldc,
               int bm, int bn)
{
    constexpr int BN     = TILEN;
    constexpr int MI     = (TILEN == 128) ? 4 : 2;
    constexpr int BBUF   = (TILEN == 128) ? 4608 : 2304;   // floats
    constexpr int BUFSZ  = 4608 + BBUF;
    constexpr int BSTR_N = (TILEN == 128) ? 136 : 72;
    constexpr int NCH    = BN / 4;
    constexpr int BITERS = (TILEN == 128) ? 4 : 2;

    const int tid = threadIdx.x;
    const int wid = tid >> 5, lane = tid & 31;
    const int g = lane >> 2, tg = lane & 3;
    const int wm = (TILEN == 128) ? (wid >> 2) : (wid >> 1);
    const int wn = (TILEN == 128) ? (wid & 3)  : (wid & 1);
    const int moff = wm * ((TILEN == 128) ? 64 : 32);

    extern __shared__ float smem[];
    const uint32_t s0 = (uint32_t)__cvta_generic_to_shared(smem);

    const int Keff = (MODE == 2) ? min(K, bm + 128) : K;
    const int T = Keff >> 5;

    float acc[MI][4][4];
    #pragma unroll
    for (int mi = 0; mi < MI; mi++)
        #pragma unroll
        for (int ni = 0; ni < 4; ni++)
            #pragma unroll
            for (int e = 0; e < 4; e++) acc[mi][ni][e] = 0.0f;

    auto load_tile = [&](int t, int st) {
        const int k0 = t * 32;
        const uint32_t au = s0 + (uint32_t)(st * BUFSZ) * 4u;
        const uint32_t bu = au + 4608u * 4u;
        #pragma unroll
        for (int i = 0; i < 4; i++) {
            int f = tid + i * 256;
            int row = f >> 3, c = f & 7;
            cp16(au + (uint32_t)(row * 36 + c * 4) * 4u,
                 A + (long)(bm + row) * lda + k0 + c * 4);
        }
        #pragma unroll
        for (int i = 0; i < BITERS; i++) {
            int f = tid + i * 256;
            if (TRANSB) {
                int row = f >> 3, c = f & 7;
                cp16(bu + (uint32_t)(row * 36 + c * 4) * 4u,
                     B + (long)(bn + row) * ldb + k0 + c * 4);
            } else {
                int kr = f / NCH, c = f % NCH;
                cp16(bu + (uint32_t)(kr * BSTR_N + c * 4) * 4u,
                     B + (long)(k0 + kr) * ldb + bn + c * 4);
            }
        }
        CP_COMMIT();
    };

    auto compute = [&](int st) {
        const float* as = smem + st * BUFSZ;
        const float* bs = as + 4608;
        #pragma unroll
        for (int ks = 0; ks < 4; ks++) {
            const int kk = ks * 8;
            uint32_t af[MI][4];
            #pragma unroll
            for (int mi = 0; mi < MI; mi++) {
                int r = moff + mi * 16 + g;
                af[mi][0] = __float_as_uint(as[r * 36 + kk + tg]);
                af[mi][1] = __float_as_uint(as[(r + 8) * 36 + kk + tg]);
                af[mi][2] = __float_as_uint(as[r * 36 + kk + tg + 4]);
                af[mi][3] = __float_as_uint(as[(r + 8) * 36 + kk + tg + 4]);
            }
            uint32_t bf[4][2];
            #pragma unroll
            for (int ni = 0; ni < 4; ni++) {
                int n = wn * 32 + ni * 8 + g;
                float r0 = TRANSB ? bs[n * 36 + kk + tg]
                                  : bs[(kk + tg) * BSTR_N + n];
                float r1 = TRANSB ? bs[n * 36 + kk + tg + 4]
                                  : bs[(kk + tg + 4) * BSTR_N + n];
                bf[ni][0] = CVTB ? f2tf(r0) : __float_as_uint(r0);
                bf[ni][1] = CVTB ? f2tf(r1) : __float_as_uint(r1);
            }
            #pragma unroll
            for (int mi = 0; mi < MI; mi++)
                #pragma unroll
                for (int ni = 0; ni < 4; ni++)
                    MMA_TF32(acc[mi][ni], af[mi], bf[ni]);
        }
    };

    // 3-stage pipeline, single barrier per iteration
    load_tile(0, 0);
    if (T > 1) load_tile(1, 1);
    int st = 0;
    for (int t = 0; t < T; t++) {
        if (t + 1 < T) { CP_WAIT1(); } else { CP_WAIT0(); }
        __syncthreads();
        if (t + 2 < T) {
            int ns = st + 2; if (ns >= 3) ns -= 3;
            load_tile(t + 2, ns);
        }
        compute(st);
        if (++st == 3) st = 0;
    }

    // ---- epilogue -----------------------------------------------------------
    #pragma unroll
    for (int mi = 0; mi < MI; mi++) {
        int r0 = bm + moff + mi * 16 + g;
        #pragma unroll
        for (int ni = 0; ni < 4; ni++) {
            int c0 = bn + wn * 32 + ni * 8 + 2 * tg;
            float e0 = acc[mi][ni][0], e1 = acc[mi][ni][1];
            float e2 = acc[mi][ni][2], e3 = acc[mi][ni][3];
            if (RELU) {
                e0 = fmaxf(e0, 0.f); e1 = fmaxf(e1, 0.f);
                e2 = fmaxf(e2, 0.f); e3 = fmaxf(e3, 0.f);
            }
            if (MODE == 1 && bn == bm) {
                if (c0     > r0)     e0 = NEGV;
                if (c0 + 1 > r0)     e1 = NEGV;
                if (c0     > r0 + 8) e2 = NEGV;
                if (c0 + 1 > r0 + 8) e3 = NEGV;
            }
            if (ROUNDC) {
                e0 = roundtf(e0); e1 = roundtf(e1);
                e2 = roundtf(e2); e3 = roundtf(e3);
            }
            *reinterpret_cast<float2*>(C + (long)r0 * ldc + c0) =
                make_float2(e0, e1);
            *reinterpret_cast<float2*>(C + (long)(r0 + 8) * ldc + c0) =
                make_float2(e2, e3);
        }
    }
}

// ---------------- generic wrapper -------------------------------------------
template<int TILEN, int TRANSB, int CVTB, int RELU, int ROUNDC, int MODE>
__global__ __launch_bounds__(256, 2)
void mgemm_k(const float* __restrict__ Abase, const float* __restrict__ Bbase,
             float* __restrict__ Cbase, int K,
             int lda, int ldb, int ldc, long sA, long sB, long sC)
{
    const int bz = blockIdx.z;
    const float* A = Abase + (long)bz * sA;
    const float* B = Bbase + (long)bz * sB;
    float*       C = Cbase + (long)bz * sC;
    const int bm = blockIdx.y * 128;
    const int bn = blockIdx.x * TILEN;

    if (MODE == 1 && bn > bm) {                  // fully masked tile: NEG fill
        const float4 nv = make_float4(NEGV, NEGV, NEGV, NEGV);
        for (int i = threadIdx.x; i < 128 * TILEN / 4; i += 256) {
            int row = i / (TILEN / 4), c4 = (i % (TILEN / 4)) * 4;
            *reinterpret_cast<float4*>(C + (long)(bm + row) * ldc + bn + c4) = nv;
        }
        return;
    }
    gemm_body<TILEN, TRANSB, CVTB, RELU, ROUNDC, MODE>(
        A, B, C, K, lda, ldb, ldc, bm, bn);
}

// ---------------- fused QKV wrapper (TILEN=128) ------------------------------
__global__ __launch_bounds__(256, 2)
void qkv_k(const float* __restrict__ A,
           const float* __restrict__ Bq, const float* __restrict__ Bk,
           const float* __restrict__ Bv,
           float* __restrict__ Cq, float* __restrict__ Ck,
           float* __restrict__ Cv)
{
    const int mat = blockIdx.x >> 3;             // 0..2 : q, k, v
    const int bn = (blockIdx.x & 7) * 128;
    const int bm = blockIdx.y * 128;
    const float* B = (mat == 0) ? Bq : (mat == 1) ? Bk : Bv;
    float*       C = (mat == 0) ? Cq : (mat == 1) ? Ck : Cv;
    gemm_body<128, 0, 1, 0, 1, 0>(A, B, C, FF, FF, HDALL, HDALL, bm, bn);
}

// ---------------- row softmax (stores tf32-rounded probs) --------------------
__global__ __launch_bounds__(256)
void softmax_k(float* __restrict__ scores)
{
    long row = blockIdx.x;
    float* p = scores + row * (long)SQ;
    int tid = threadIdx.x;

    float v[8];
    float m = -INFINITY;
    #pragma unroll
    for (int i = 0; i < 8; i++) { v[i] = p[tid + i * 256]; m = fmaxf(m, v[i]); }
    __shared__ float red[256];
    red[tid] = m; __syncthreads();
    #pragma unroll
    for (int s = 128; s > 0; s >>= 1) {
        if (tid < s) red[tid] = fmaxf(red[tid], red[tid + s]);
        __syncthreads();
    }
    m = red[0];
    __syncthreads();
    float sum = 0.0f;
    #pragma unroll
    for (int i = 0; i < 8; i++) { v[i] = __expf(v[i] - m); sum += v[i]; }
    red[tid] = sum; __syncthreads();
    #pragma unroll
    for (int s = 128; s > 0; s >>= 1) {
        if (tid < s) red[tid] += red[tid + s];
        __syncthreads();
    }
    float inv = 1.0f / red[0];
    #pragma unroll
    for (int i = 0; i < 8; i++) p[tid + i * 256] = roundtf(v[i] * inv);
}

// ---------------- launch -----------------------------------------------------
#define SM128 110592    // 3 * (4608 + 4608) * 4
#define SM64   82944    // 3 * (4608 + 2304) * 4

extern "C" void kernel_launch(void* const* d_in, const int* in_sizes, int n_in,
                              void* d_out, int out_size)
{
    const int*   x    = (const int*)  d_in[0];
    const float* emb  = (const float*)d_in[1];
    const float* ff_w = (const float*)d_in[2];
    const float* q_w  = (const float*)d_in[3];
    const float* k_w  = (const float*)d_in[4];
    const float* v_w  = (const float*)d_in[5];
    const float* o_w  = (const float*)d_in[6];
    float* out = (float*)d_out;

    float *h, *hf, *q, *k, *v, *o, *sc;
    cudaGetSymbolAddress((void**)&h,  g_h);
    cudaGetSymbolAddress((void**)&hf, g_hf);
    cudaGetSymbolAddress((void**)&q,  g_q);
    cudaGetSymbolAddress((void**)&k,  g_k);
    cudaGetSymbolAddress((void**)&v,  g_v);
    cudaGetSymbolAddress((void**)&o,  g_o);
    cudaGetSymbolAddress((void**)&sc, g_sc);

    cudaFuncSetAttribute(mgemm_k<128,0,1,1,1,0>, cudaFuncAttributeMaxDynamicSharedMemorySize, SM128);
    cudaFuncSetAttribute(qkv_k,                  cudaFuncAttributeMaxDynamicSharedMemorySize, SM128);
    cudaFuncSetAttribute(mgemm_k<128,1,0,0,0,1>, cudaFuncAttributeMaxDynamicSharedMemorySize, SM128);
    cudaFuncSetAttribute(mgemm_k<64,0,0,0,1,2>,  cudaFuncAttributeMaxDynamicSharedMemorySize, SM64);
    cudaFuncSetAttribute(mgemm_k<64,0,1,0,1,0>,  cudaFuncAttributeMaxDynamicSharedMemorySize, SM64);
    cudaFuncSetAttribute(mgemm_k<128,1,1,0,0,0>, cudaFuncAttributeMaxDynamicSharedMemorySize, SM128);

    embed_k<<<SQ, 256>>>(x, emb, h);

    for (int l = 0; l < NL; l++) {
        // hf = relu(h @ ff_w[l]) : [S,E]x[E,F]
        mgemm_k<128,0,1,1,1,0><<<dim3(FF/128, SQ/128, 1), 256, SM128>>>(
            h, ff_w + (long)l * EM * FF, hf,
            EM, EM, FF, FF, 0, 0, 0);

        // q,k,v = hf @ {q_w,k_w,v_w}[l] fused : grid 24x16 = 384 CTAs
        qkv_k<<<dim3(3 * HDALL / 128, SQ/128, 1), 256, SM128>>>(
            hf,
            q_w + (long)l * FF * HDALL,
            k_w + (long)l * FF * HDALL,
            v_w + (long)l * FF * HDALL,
            q, k, v);

        // scores[h] = q_h @ k_h^T (causal), batched over heads in z
        mgemm_k<128,1,0,0,0,1><<<dim3(SQ/128, SQ/128, NH), 256, SM128>>>(
            q, k, sc,
            HD, HDALL, HDALL, SQ,
            (long)HD, (long)HD, (long)SQ * SQ);

        softmax_k<<<NH * SQ, 256>>>(sc);

        // o[h] = P_h @ v_h, K truncated by causality
        mgemm_k<64,0,0,0,1,2><<<dim3(HD/64, SQ/128, NH), 256, SM64>>>(
            sc, v, o,
            SQ, SQ, HDALL, HDALL,
            (long)SQ * SQ, (long)HD, (long)HD);

        // h = o @ o_w[l]
        mgemm_k<64,0,1,0,1,0><<<dim3(EM/64, SQ/128, 1), 256, SM64>>>(
            o, o_w + (long)l * HDALL * EM, h,
            HDALL, HDALL, EM, EM, 0, 0, 0);
    }

    // logits = h @ emb^T
    mgemm_k<128,1,1,0,0,0><<<dim3(VC/128, SQ/128, 1), 256, SM128>>>(
        h, emb, out,
        EM, EM, EM, VC, 0, 0, 0);
}

// round 12
// speedup vs baseline: 4.0678x; 1.0716x over previous
#include <cuda_runtime.h>
#include <cuda_bf16.h>
#include <math.h>
#include <stdint.h>

#define SQ   2048
#define EM   1024
#define FF   4096
#define NH   8
#define HD   128
#define NL   4
#define VC   32000
#define NEGV (-1.0e9f)
#define HDALL (NH * HD)

// ---------------- scratch (device globals) ----------------------------------
__device__ float g_h [SQ * EM];
__device__ float g_hf[SQ * FF];
__device__ float g_q [SQ * NH * HD];
__device__ float g_k [SQ * NH * HD];
__device__ float g_v [SQ * NH * HD];
__device__ float g_o [SQ * NH * HD];

// ---------------- helpers ----------------------------------------------------
__device__ __forceinline__ uint32_t f2tf(float f) {
    uint32_t r;
    asm("cvt.rna.tf32.f32 %0, %1;" : "=r"(r) : "f"(f));
    return r;
}
__device__ __forceinline__ float roundtf(float f) {
    return __uint_as_float(f2tf(f));
}
__device__ __forceinline__ void cp16(uint32_t dst, const float* src) {
    asm volatile("cp.async.cg.shared.global [%0], [%1], 16;"
                 :: "r"(dst), "l"(src) : "memory");
}
#define CP_COMMIT() asm volatile("cp.async.commit_group;" ::: "memory")
#define CP_WAIT0()  asm volatile("cp.async.wait_group 0;" ::: "memory")
#define CP_WAIT1()  asm volatile("cp.async.wait_group 1;" ::: "memory")

#define MMA_TF32(d, a, b) \
    asm volatile("mma.sync.aligned.m16n8k8.row.col.f32.tf32.tf32.f32 " \
                 "{%0,%1,%2,%3},{%4,%5,%6,%7},{%8,%9},{%0,%1,%2,%3};" \
                 : "+f"((d)[0]), "+f"((d)[1]), "+f"((d)[2]), "+f"((d)[3]) \
                 : "r"((a)[0]), "r"((a)[1]), "r"((a)[2]), "r"((a)[3]), \
                   "r"((b)[0]), "r"((b)[1]))

// exp(x), x <= 0, via FMA-pipe 2^f Taylor (deg 6, rel err ~1e-5). No MUFU.
__device__ __forceinline__ float fexp(float x) {
    float y = fmaxf(x * 1.4426950408889634f, -127.0f);
    float n = floorf(y);
    float f = y - n;
    float p = 0.00015403530393f;
    p = fmaf(p, f, 0.0013333558146f);
    p = fmaf(p, f, 0.0096181291076f);
    p = fmaf(p, f, 0.0555041086648f);
    p = fmaf(p, f, 0.2402265069591f);
    p = fmaf(p, f, 0.6931471805599f);
    p = fmaf(p, f, 1.0f);
    int ni = (int)n;
    return p * __int_as_float((ni + 127) << 23);
}

// ---------------- embedding gather (rounds to tf32) --------------------------
__global__ void embed_k(const int* __restrict__ x, const float* __restrict__ emb,
                        float* __restrict__ h)
{
    int s = blockIdx.x;
    int id = x[s];
    const float4* src = reinterpret_cast<const float4*>(emb + (long)id * EM);
    float4 v = src[threadIdx.x];
    v.x = roundtf(v.x); v.y = roundtf(v.y);
    v.z = roundtf(v.z); v.w = roundtf(v.w);
    reinterpret_cast<float4*>(h + (long)s * EM)[threadIdx.x] = v;
}

// ---------------- GEMM body: 128 x TILEN tile, BK=32, 3-stage pipeline ------
template<int TILEN, int TRANSB, int CVTB, int RELU, int ROUNDC>
__device__ __forceinline__
void gemm_body(const float* __restrict__ A, const float* __restrict__ B,
               float* __restrict__ C, int K, int lda, int ldb, int ldc,
               int bm, int bn)
{
    constexpr int BN     = TILEN;
    constexpr int MI     = (TILEN == 128) ? 4 : 2;
    constexpr int BBUF   = (TILEN == 128) ? 4608 : 2304;
    constexpr int BUFSZ  = 4608 + BBUF;
    constexpr int BSTR_N = (TILEN == 128) ? 136 : 72;
    constexpr int NCH    = BN / 4;
    constexpr int BITERS = (TILEN == 128) ? 4 : 2;

    const int tid = threadIdx.x;
    const int wid = tid >> 5, lane = tid & 31;
    const int g = lane >> 2, tg = lane & 3;
    const int wm = (TILEN == 128) ? (wid >> 2) : (wid >> 1);
    const int wn = (TILEN == 128) ? (wid & 3)  : (wid & 1);
    const int moff = wm * ((TILEN == 128) ? 64 : 32);

    extern __shared__ float smem[];
    const uint32_t s0 = (uint32_t)__cvta_generic_to_shared(smem);

    const int T = K >> 5;

    float acc[MI][4][4];
    #pragma unroll
    for (int mi = 0; mi < MI; mi++)
        #pragma unroll
        for (int ni = 0; ni < 4; ni++)
            #pragma unroll
            for (int e = 0; e < 4; e++) acc[mi][ni][e] = 0.0f;

    auto load_tile = [&](int t, int st) {
        const int k0 = t * 32;
        const uint32_t au = s0 + (uint32_t)(st * BUFSZ) * 4u;
        const uint32_t bu = au + 4608u * 4u;
        #pragma unroll
        for (int i = 0; i < 4; i++) {
            int f = tid + i * 256;
            int row = f >> 3, c = f & 7;
            cp16(au + (uint32_t)(row * 36 + c * 4) * 4u,
                 A + (long)(bm + row) * lda + k0 + c * 4);
        }
        #pragma unroll
        for (int i = 0; i < BITERS; i++) {
            int f = tid + i * 256;
            if (TRANSB) {
                int row = f >> 3, c = f & 7;
                cp16(bu + (uint32_t)(row * 36 + c * 4) * 4u,
                     B + (long)(bn + row) * ldb + k0 + c * 4);
            } else {
                int kr = f / NCH, c = f % NCH;
                cp16(bu + (uint32_t)(kr * BSTR_N + c * 4) * 4u,
                     B + (long)(k0 + kr) * ldb + bn + c * 4);
            }
        }
        CP_COMMIT();
    };

    auto compute = [&](int st) {
        const float* as = smem + st * BUFSZ;
        const float* bs = as + 4608;
        #pragma unroll
        for (int ks = 0; ks < 4; ks++) {
            const int kk = ks * 8;
            uint32_t af[MI][4];
            #pragma unroll
            for (int mi = 0; mi < MI; mi++) {
                int r = moff + mi * 16 + g;
                af[mi][0] = __float_as_uint(as[r * 36 + kk + tg]);
                af[mi][1] = __float_as_uint(as[(r + 8) * 36 + kk + tg]);
                af[mi][2] = __float_as_uint(as[r * 36 + kk + tg + 4]);
                af[mi][3] = __float_as_uint(as[(r + 8) * 36 + kk + tg + 4]);
            }
            uint32_t bf[4][2];
            #pragma unroll
            for (int ni = 0; ni < 4; ni++) {
                int n = wn * 32 + ni * 8 + g;
                float r0 = TRANSB ? bs[n * 36 + kk + tg]
                                  : bs[(kk + tg) * BSTR_N + n];
                float r1 = TRANSB ? bs[n * 36 + kk + tg + 4]
                                  : bs[(kk + tg + 4) * BSTR_N + n];
                bf[ni][0] = CVTB ? f2tf(r0) : __float_as_uint(r0);
                bf[ni][1] = CVTB ? f2tf(r1) : __float_as_uint(r1);
            }
            #pragma unroll
            for (int mi = 0; mi < MI; mi++)
                #pragma unroll
                for (int ni = 0; ni < 4; ni++)
                    MMA_TF32(acc[mi][ni], af[mi], bf[ni]);
        }
    };

    load_tile(0, 0);
    if (T > 1) load_tile(1, 1);
    int st = 0;
    for (int t = 0; t < T; t++) {
        if (t + 1 < T) { CP_WAIT1(); } else { CP_WAIT0(); }
        __syncthreads();
        if (t + 2 < T) {
            int ns = st + 2; if (ns >= 3) ns -= 3;
            load_tile(t + 2, ns);
        }
        compute(st);
        if (++st == 3) st = 0;
    }

    #pragma unroll
    for (int mi = 0; mi < MI; mi++) {
        int r0 = bm + moff + mi * 16 + g;
        #pragma unroll
        for (int ni = 0; ni < 4; ni++) {
            int c0 = bn + wn * 32 + ni * 8 + 2 * tg;
            float e0 = acc[mi][ni][0], e1 = acc[mi][ni][1];
            float e2 = acc[mi][ni][2], e3 = acc[mi][ni][3];
            if (RELU) {
                e0 = fmaxf(e0, 0.f); e1 = fmaxf(e1, 0.f);
                e2 = fmaxf(e2, 0.f); e3 = fmaxf(e3, 0.f);
            }
            if (ROUNDC) {
                e0 = roundtf(e0); e1 = roundtf(e1);
                e2 = roundtf(e2); e3 = roundtf(e3);
            }
            *reinterpret_cast<float2*>(C + (long)r0 * ldc + c0) =
                make_float2(e0, e1);
            *reinterpret_cast<float2*>(C + (long)(r0 + 8) * ldc + c0) =
                make_float2(e2, e3);
        }
    }
}

template<int TILEN, int TRANSB, int CVTB, int RELU, int ROUNDC>
__global__ __launch_bounds__(256, 2)
void mgemm_k(const float* __restrict__ A, const float* __restrict__ B,
             float* __restrict__ C, int K, int lda, int ldb, int ldc)
{
    gemm_body<TILEN, TRANSB, CVTB, RELU, ROUNDC>(
        A, B, C, K, lda, ldb, ldc, blockIdx.y * 128, blockIdx.x * TILEN);
}

__global__ __launch_bounds__(256, 2)
void qkv_k(const float* __restrict__ A,
           const float* __restrict__ Bq, const float* __restrict__ Bk,
           const float* __restrict__ Bv,
           float* __restrict__ Cq, float* __restrict__ Ck,
           float* __restrict__ Cv)
{
    const int mat = blockIdx.x >> 3;
    const int bn = (blockIdx.x & 7) * 128;
    const int bm = blockIdx.y * 128;
    const float* B = (mat == 0) ? Bq : (mat == 1) ? Bk : Bv;
    float*       C = (mat == 0) ? Cq : (mat == 1) ? Ck : Cv;
    gemm_body<128, 0, 1, 0, 1>(A, B, C, FF, FF, HDALL, HDALL, bm, bn);
}

// ================= fused flash attention =====================================
// Grid (16, NH). CTA handles head=blockIdx.y, q sub-blocks {j, 31-j} of 64 rows
// (balanced: each CTA processes exactly 33 kv tiles of 64).
// Warps 2(M) x 4(N). QK: warp 32q x 16kv. PV: warp 32q x 32d.
// smem floats: Q[64][132] @0 | K dbuf 2x[64][132] @8448 | V dbuf @25344
//              P[64][68] @42240 | redmax @46592 | redsum @46848 | end 47104
#define FL_Q   0
#define FL_K   8448
#define FL_V   25344
#define FL_P   42240
#define FL_RM  46592
#define FL_RS  46848
#define FL_SM  (47104 * 4)

__global__ __launch_bounds__(256, 1)
void flash_k(const float* __restrict__ q, const float* __restrict__ k,
             const float* __restrict__ v, float* __restrict__ o)
{
    const int head = blockIdx.y;
    const int pair = blockIdx.x;
    const int tid = threadIdx.x;
    const int wid = tid >> 5, lane = tid & 31;
    const int g = lane >> 2, tg = lane & 3;
    const int wm = wid >> 2, wn = wid & 3;

    extern __shared__ float sm[];
    const uint32_t su = (uint32_t)__cvta_generic_to_shared(sm);

    const float* qh = q + head * HD;
    const float* kh = k + head * HD;
    const float* vh = v + head * HD;

    for (int half = 0; half < 2; half++) {
        const int j  = half ? (31 - pair) : pair;
        const int r0 = j * 64;
        const int ntiles = j + 1;

        // ---- load Q sub-block [64][128] -> [64][132]
        #pragma unroll
        for (int i = 0; i < 8; i++) {
            int f = tid + i * 256;
            int row = f >> 5, c = f & 31;
            cp16(su + (uint32_t)(FL_Q + row * 132 + c * 4) * 4u,
                 qh + (long)(r0 + row) * HDALL + c * 4);
        }
        // ---- prologue: KV tile 0 -> buf 0
        {
            #pragma unroll
            for (int i = 0; i < 8; i++) {
                int f = tid + i * 256;
                int row = f >> 5, c = f & 31;
                cp16(su + (uint32_t)(FL_K + row * 132 + c * 4) * 4u,
                     kh + (long)row * HDALL + c * 4);
                cp16(su + (uint32_t)(FL_V + row * 132 + c * 4) * 4u,
                     vh + (long)row * HDALL + c * 4);
            }
            CP_COMMIT();
        }

        float oacc[2][4][4];
        #pragma unroll
        for (int mi = 0; mi < 2; mi++)
            #pragma unroll
            for (int ni = 0; ni < 4; ni++)
                #pragma unroll
                for (int e = 0; e < 4; e++) oacc[mi][ni][e] = 0.0f;
        float mrow[2][2], lrow[2][2];
        #pragma unroll
        for (int mi = 0; mi < 2; mi++) {
            mrow[mi][0] = -3.0e38f; mrow[mi][1] = -3.0e38f;
            lrow[mi][0] = 0.0f;     lrow[mi][1] = 0.0f;
        }

        for (int t = 0; t < ntiles; t++) {
            const int buf = t & 1;
            CP_WAIT0();
            __syncthreads();                       // KV[t] visible; prev reads done
            if (t + 1 < ntiles) {                  // prefetch KV[t+1]
                const int nb = (t + 1) & 1;
                const long kv0 = (long)(t + 1) * 64;
                #pragma unroll
                for (int i = 0; i < 8; i++) {
                    int f = tid + i * 256;
                    int row = f >> 5, c = f & 31;
                    cp16(su + (uint32_t)(FL_K + nb * 8448 + row * 132 + c * 4) * 4u,
                         kh + (kv0 + row) * HDALL + c * 4);
                    cp16(su + (uint32_t)(FL_V + nb * 8448 + row * 132 + c * 4) * 4u,
                         vh + (kv0 + row) * HDALL + c * 4);
                }
                CP_COMMIT();
            }

            const float* Qs = sm + FL_Q;
            const float* Ks = sm + FL_K + buf * 8448;
            const float* Vs = sm + FL_V + buf * 8448;

            // ---- QK^T : S[64][64], warp tile 32x16
            float sacc[2][2][4];
            #pragma unroll
            for (int mi = 0; mi < 2; mi++)
                #pragma unroll
                for (int ni = 0; ni < 2; ni++)
                    #pragma unroll
                    for (int e = 0; e < 4; e++) sacc[mi][ni][e] = 0.0f;
            #pragma unroll
            for (int kc = 0; kc < 16; kc++) {
                const int kk = kc * 8;
                uint32_t af[2][4];
                #pragma unroll
                for (int mi = 0; mi < 2; mi++) {
                    int r = wm * 32 + mi * 16 + g;
                    af[mi][0] = __float_as_uint(Qs[r * 132 + kk + tg]);
                    af[mi][1] = __float_as_uint(Qs[(r + 8) * 132 + kk + tg]);
                    af[mi][2] = __float_as_uint(Qs[r * 132 + kk + tg + 4]);
                    af[mi][3] = __float_as_uint(Qs[(r + 8) * 132 + kk + tg + 4]);
                }
                uint32_t bf[2][2];
                #pragma unroll
                for (int ni = 0; ni < 2; ni++) {
                    int n = wn * 16 + ni * 8 + g;
                    bf[ni][0] = __float_as_uint(Ks[n * 132 + kk + tg]);
                    bf[ni][1] = __float_as_uint(Ks[n * 132 + kk + tg + 4]);
                }
                #pragma unroll
                for (int mi = 0; mi < 2; mi++)
                    #pragma unroll
                    for (int ni = 0; ni < 2; ni++)
                        MMA_TF32(sacc[mi][ni], af[mi], bf[ni]);
            }

            // ---- causal mask (only the final/diagonal tile)
            if (t == ntiles - 1) {
                #pragma unroll
                for (int mi = 0; mi < 2; mi++) {
                    int ra = wm * 32 + mi * 16 + g;
                    #pragma unroll
                    for (int ni = 0; ni < 2; ni++) {
                        int c0 = wn * 16 + ni * 8 + 2 * tg;
                        if (c0     > ra)     sacc[mi][ni][0] = -3.0e38f;
                        if (c0 + 1 > ra)     sacc[mi][ni][1] = -3.0e38f;
                        if (c0     > ra + 8) sacc[mi][ni][2] = -3.0e38f;
                        if (c0 + 1 > ra + 8) sacc[mi][ni][3] = -3.0e38f;
                    }
                }
            }

            // ---- row max: thread -> quad -> cross-warp via smem
            #pragma unroll
            for (int mi = 0; mi < 2; mi++) {
                float pa = fmaxf(fmaxf(sacc[mi][0][0], sacc[mi][0][1]),
                                 fmaxf(sacc[mi][1][0], sacc[mi][1][1]));
                float pb = fmaxf(fmaxf(sacc[mi][0][2], sacc[mi][0][3]),
                                 fmaxf(sacc[mi][1][2], sacc[mi][1][3]));
                pa = fmaxf(pa, __shfl_xor_sync(0xffffffffu, pa, 1));
                pa = fmaxf(pa, __shfl_xor_sync(0xffffffffu, pa, 2));
                pb = fmaxf(pb, __shfl_xor_sync(0xffffffffu, pb, 1));
                pb = fmaxf(pb, __shfl_xor_sync(0xffffffffu, pb, 2));
                if (tg == 0) {
                    int ra = wm * 32 + mi * 16 + g;
                    sm[FL_RM + ra * 4 + wn]       = pa;
                    sm[FL_RM + (ra + 8) * 4 + wn] = pb;
                }
            }
            __syncthreads();

            // ---- m update, exp, P store, partial sums
            float scal[2][2], mnew[2][2];
            #pragma unroll
            for (int mi = 0; mi < 2; mi++) {
                #pragma unroll
                for (int h2 = 0; h2 < 2; h2++) {
                    int r = wm * 32 + mi * 16 + g + h2 * 8;
                    float rm = fmaxf(fmaxf(sm[FL_RM + r * 4 + 0], sm[FL_RM + r * 4 + 1]),
                                     fmaxf(sm[FL_RM + r * 4 + 2], sm[FL_RM + r * 4 + 3]));
                    float mn = fmaxf(mrow[mi][h2], rm);
                    scal[mi][h2] = fexp(mrow[mi][h2] - mn);
                    mnew[mi][h2] = mn;
                }
            }
            float psum[2][2] = {{0.f, 0.f}, {0.f, 0.f}};
            #pragma unroll
            for (int mi = 0; mi < 2; mi++) {
                int ra = wm * 32 + mi * 16 + g;
                #pragma unroll
                for (int ni = 0; ni < 2; ni++) {
                    int c0 = wn * 16 + ni * 8 + 2 * tg;
                    float p0 = fexp(sacc[mi][ni][0] - mnew[mi][0]);
                    float p1 = fexp(sacc[mi][ni][1] - mnew[mi][0]);
                    float p2 = fexp(sacc[mi][ni][2] - mnew[mi][1]);
                    float p3 = fexp(sacc[mi][ni][3] - mnew[mi][1]);
                    psum[mi][0] += p0 + p1;
                    psum[mi][1] += p2 + p3;
                    *reinterpret_cast<float2*>(sm + FL_P + ra * 68 + c0) =
                        make_float2(roundtf(p0), roundtf(p1));
                    *reinterpret_cast<float2*>(sm + FL_P + (ra + 8) * 68 + c0) =
                        make_float2(roundtf(p2), roundtf(p3));
                }
            }
            #pragma unroll
            for (int mi = 0; mi < 2; mi++) {
                float sa = psum[mi][0], sb = psum[mi][1];
                sa += __shfl_xor_sync(0xffffffffu, sa, 1);
                sa += __shfl_xor_sync(0xffffffffu, sa, 2);
                sb += __shfl_xor_sync(0xffffffffu, sb, 1);
                sb += __shfl_xor_sync(0xffffffffu, sb, 2);
                if (tg == 0) {
                    int ra = wm * 32 + mi * 16 + g;
                    sm[FL_RS + ra * 4 + wn]       = sa;
                    sm[FL_RS + (ra + 8) * 4 + wn] = sb;
                }
            }
            __syncthreads();                       // P + redsum visible

            // ---- l update + O rescale
            #pragma unroll
            for (int mi = 0; mi < 2; mi++) {
                #pragma unroll
                for (int h2 = 0; h2 < 2; h2++) {
                    int r = wm * 32 + mi * 16 + g + h2 * 8;
                    float rs = sm[FL_RS + r * 4 + 0] + sm[FL_RS + r * 4 + 1]
                             + sm[FL_RS + r * 4 + 2] + sm[FL_RS + r * 4 + 3];
                    lrow[mi][h2] = lrow[mi][h2] * scal[mi][h2] + rs;
                    mrow[mi][h2] = mnew[mi][h2];
                }
                #pragma unroll
                for (int ni = 0; ni < 4; ni++) {
                    oacc[mi][ni][0] *= scal[mi][0];
                    oacc[mi][ni][1] *= scal[mi][0];
                    oacc[mi][ni][2] *= scal[mi][1];
                    oacc[mi][ni][3] *= scal[mi][1];
                }
            }

            // ---- PV : O += P[64][64] @ V[64][128], warp tile 32x32
            const float* Ps = sm + FL_P;
            #pragma unroll
            for (int kc = 0; kc < 8; kc++) {
                const int kk = kc * 8;
                uint32_t af[2][4];
                #pragma unroll
                for (int mi = 0; mi < 2; mi++) {
                    int r = wm * 32 + mi * 16 + g;
                    af[mi][0] = __float_as_uint(Ps[r * 68 + kk + tg]);
                    af[mi][1] = __float_as_uint(Ps[(r + 8) * 68 + kk + tg]);
                    af[mi][2] = __float_as_uint(Ps[r * 68 + kk + tg + 4]);
                    af[mi][3] = __float_as_uint(Ps[(r + 8) * 68 + kk + tg + 4]);
                }
                uint32_t bf[4][2];
                #pragma unroll
                for (int ni = 0; ni < 4; ni++) {
                    int n = wn * 32 + ni * 8 + g;
                    bf[ni][0] = __float_as_uint(Vs[(kk + tg) * 132 + n]);
                    bf[ni][1] = __float_as_uint(Vs[(kk + tg + 4) * 132 + n]);
                }
                #pragma unroll
                for (int mi = 0; mi < 2; mi++)
                    #pragma unroll
                    for (int ni = 0; ni < 4; ni++)
                        MMA_TF32(oacc[mi][ni], af[mi], bf[ni]);
            }
        }

        // ---- epilogue: O /= l, round, store
        #pragma unroll
        for (int mi = 0; mi < 2; mi++) {
            float ia = 1.0f / lrow[mi][0];
            float ib = 1.0f / lrow[mi][1];
            int ra = r0 + wm * 32 + mi * 16 + g;
            #pragma unroll
            for (int ni = 0; ni < 4; ni++) {
                int c0 = head * HD + wn * 32 + ni * 8 + 2 * tg;
                *reinterpret_cast<float2*>(o + (long)ra * HDALL + c0) =
                    make_float2(roundtf(oacc[mi][ni][0] * ia),
                                roundtf(oacc[mi][ni][1] * ia));
                *reinterpret_cast<float2*>(o + (long)(ra + 8) * HDALL + c0) =
                    make_float2(roundtf(oacc[mi][ni][2] * ib),
                                roundtf(oacc[mi][ni][3] * ib));
            }
        }
        __syncthreads();                            // Q/KV reuse guard
    }
}

// ---------------- launch -----------------------------------------------------
#define SM128 110592
#define SM64   82944

extern "C" void kernel_launch(void* const* d_in, const int* in_sizes, int n_in,
                              void* d_out, int out_size)
{
    const int*   x    = (const int*)  d_in[0];
    const float* emb  = (const float*)d_in[1];
    const float* ff_w = (const float*)d_in[2];
    const float* q_w  = (const float*)d_in[3];
    const float* k_w  = (const float*)d_in[4];
    const float* v_w  = (const float*)d_in[5];
    const float* o_w  = (const float*)d_in[6];
    float* out = (float*)d_out;

    float *h, *hf, *q, *k, *v, *o;
    cudaGetSymbolAddress((void**)&h,  g_h);
    cudaGetSymbolAddress((void**)&hf, g_hf);
    cudaGetSymbolAddress((void**)&q,  g_q);
    cudaGetSymbolAddress((void**)&k,  g_k);
    cudaGetSymbolAddress((void**)&v,  g_v);
    cudaGetSymbolAddress((void**)&o,  g_o);

    cudaFuncSetAttribute(mgemm_k<128,0,1,1,1>, cudaFuncAttributeMaxDynamicSharedMemorySize, SM128);
    cudaFuncSetAttribute(qkv_k,                cudaFuncAttributeMaxDynamicSharedMemorySize, SM128);
    cudaFuncSetAttribute(mgemm_k<64,0,1,0,1>,  cudaFuncAttributeMaxDynamicSharedMemorySize, SM64);
    cudaFuncSetAttribute(mgemm_k<128,1,1,0,0>, cudaFuncAttributeMaxDynamicSharedMemorySize, SM128);
    cudaFuncSetAttribute(flash_k,              cudaFuncAttributeMaxDynamicSharedMemorySize, FL_SM);

    embed_k<<<SQ, 256>>>(x, emb, h);

    for (int l = 0; l < NL; l++) {
        // hf = relu(h @ ff_w[l])
        mgemm_k<128,0,1,1,1><<<dim3(FF/128, SQ/128, 1), 256, SM128>>>(
            h, ff_w + (long)l * EM * FF, hf, EM, EM, FF, FF);

        // q,k,v fused
        qkv_k<<<dim3(3 * HDALL / 128, SQ/128, 1), 256, SM128>>>(
            hf,
            q_w + (long)l * FF * HDALL,
            k_w + (long)l * FF * HDALL,
            v_w + (long)l * FF * HDALL,
            q, k, v);

        // fused causal attention: scores + softmax + PV
        flash_k<<<dim3(16, NH, 1), 256, FL_SM>>>(q, k, v, o);

        // h = o @ o_w[l]
        mgemm_k<64,0,1,0,1><<<dim3(EM/64, SQ/128, 1), 256, SM64>>>(
            o, o_w + (long)l * HDALL * EM, h, HDALL, HDALL, EM, EM);
    }

    // logits = h @ emb^T
    mgemm_k<128,1,1,0,0><<<dim3(VC/128, SQ/128, 1), 256, SM128>>>(
        h, emb, out, EM, EM, EM, VC);
}

// round 13
// speedup vs baseline: 4.3072x; 1.0588x over previous
#include <cuda_runtime.h>
#include <cuda_bf16.h>
#include <math.h>
#include <stdint.h>

#define SQ   2048
#define EM   1024
#define FF   4096
#define NH   8
#define HD   128
#define NL   4
#define VC   32000
#define HDALL (NH * HD)

// ---------------- scratch (device globals) ----------------------------------
__device__ float g_h [SQ * EM];
__device__ float g_hf[SQ * FF];
__device__ float g_q [SQ * HDALL];
__device__ float g_k [SQ * HDALL];
__device__ float g_v [SQ * HDALL];
__device__ float g_o [SQ * HDALL];
// transposed + tf32-rounded weights
__device__ float g_wff[NL * FF * EM];        // [F][E]
__device__ float g_wq [NL * HDALL * FF];     // [HD_ALL][F]
__device__ float g_wk [NL * HDALL * FF];
__device__ float g_wv [NL * HDALL * FF];
__device__ float g_wo [NL * EM * HDALL];     // [E][HD_ALL]
__device__ float g_embr[(size_t)VC * EM];    // rounded, layout unchanged [V][E]

// ---------------- helpers ----------------------------------------------------
__device__ __forceinline__ uint32_t f2tf(float f) {
    uint32_t r;
    asm("cvt.rna.tf32.f32 %0, %1;" : "=r"(r) : "f"(f));
    return r;
}
__device__ __forceinline__ float roundtf(float f) {
    return __uint_as_float(f2tf(f));
}
__device__ __forceinline__ void cp16(uint32_t dst, const float* src) {
    asm volatile("cp.async.cg.shared.global [%0], [%1], 16;"
                 :: "r"(dst), "l"(src) : "memory");
}
#define CP_COMMIT() asm volatile("cp.async.commit_group;" ::: "memory")
#define CP_WAIT0()  asm volatile("cp.async.wait_group 0;" ::: "memory")
#define CP_WAIT1()  asm volatile("cp.async.wait_group 1;" ::: "memory")

#define MMA_TF32(d, a0, a1, a2, a3, b0, b1) \
    asm volatile("mma.sync.aligned.m16n8k8.row.col.f32.tf32.tf32.f32 " \
                 "{%0,%1,%2,%3},{%4,%5,%6,%7},{%8,%9},{%0,%1,%2,%3};" \
                 : "+f"((d)[0]), "+f"((d)[1]), "+f"((d)[2]), "+f"((d)[3]) \
                 : "r"(a0), "r"(a1), "r"(a2), "r"(a3), "r"(b0), "r"(b1))

#define LDSM_X4(r, a) \
    asm volatile("ldmatrix.sync.aligned.m8n8.x4.shared.b16 {%0,%1,%2,%3}, [%4];" \
                 : "=r"((r)[0]), "=r"((r)[1]), "=r"((r)[2]), "=r"((r)[3]) \
                 : "r"(a))

// exp(x), x <= 0, FMA-pipe 2^f (deg 6, rel err ~1e-5)
__device__ __forceinline__ float fexp(float x) {
    float y = fmaxf(x * 1.4426950408889634f, -127.0f);
    float n = floorf(y);
    float f = y - n;
    float p = 0.00015403530393f;
    p = fmaf(p, f, 0.0013333558146f);
    p = fmaf(p, f, 0.0096181291076f);
    p = fmaf(p, f, 0.0555041086648f);
    p = fmaf(p, f, 0.2402265069591f);
    p = fmaf(p, f, 0.6931471805599f);
    p = fmaf(p, f, 1.0f);
    return p * __int_as_float(((int)n + 127) << 23);
}

// ---------------- prep: transpose+round / round ------------------------------
// src [R][C] -> dst [C][R], tf32-rounded. grid (C/32, R/32), block (32,8)
__global__ void trn_k(const float* __restrict__ src, float* __restrict__ dst,
                      int R, int C)
{
    __shared__ float t[32][33];
    const int r0 = blockIdx.y * 32, c0 = blockIdx.x * 32;
    const int tx = threadIdx.x, ty = threadIdx.y;
    #pragma unroll
    for (int i = 0; i < 4; i++)
        t[ty + 8 * i][tx] = roundtf(src[(long)(r0 + ty + 8 * i) * C + c0 + tx]);
    __syncthreads();
    #pragma unroll
    for (int i = 0; i < 4; i++)
        dst[(long)(c0 + ty + 8 * i) * R + r0 + tx] = t[tx][ty + 8 * i];
}

__global__ void rnd_k(const float* __restrict__ src, float* __restrict__ dst)
{
    long i = ((long)blockIdx.x * 256 + threadIdx.x);
    float4 v = reinterpret_cast<const float4*>(src)[i];
    v.x = roundtf(v.x); v.y = roundtf(v.y);
    v.z = roundtf(v.z); v.w = roundtf(v.w);
    reinterpret_cast<float4*>(dst)[i] = v;
}

// ---------------- embedding gather (rounds to tf32) --------------------------
__global__ void embed_k(const int* __restrict__ x, const float* __restrict__ emb,
                        float* __restrict__ h)
{
    int s = blockIdx.x;
    int id = x[s];
    float4 v = reinterpret_cast<const float4*>(emb + (long)id * EM)[threadIdx.x];
    v.x = roundtf(v.x); v.y = roundtf(v.y);
    v.z = roundtf(v.z); v.w = roundtf(v.w);
    reinterpret_cast<float4*>(h + (long)s * EM)[threadIdx.x] = v;
}

// ---------------- GEMM body: 128 x TILEN, BK=32, 3-stage, ldmatrix ----------
// A [M][K] row-major (k-contig), B [N][K] row-major (k-contig), pre-rounded.
template<int TILEN, int RELU, int ROUNDC>
__device__ __forceinline__
void gemm_body(const float* __restrict__ A, const float* __restrict__ B,
               float* __restrict__ C, int K, int lda, int ldb, int ldc,
               int bm, int bn)
{
    constexpr int MI     = (TILEN == 128) ? 4 : 2;
    constexpr int BBUF   = (TILEN == 128) ? 4608 : 2304;
    constexpr int BUFSZ  = 4608 + BBUF;
    constexpr int BITERS = (TILEN == 128) ? 4 : 2;

    const int tid = threadIdx.x;
    const int wid = tid >> 5, lane = tid & 31;
    const int g = lane >> 2, tg = lane & 3;
    const int wm = (TILEN == 128) ? (wid >> 2) : (wid >> 1);
    const int wn = (TILEN == 128) ? (wid & 3)  : (wid & 1);
    const int moff = wm * ((TILEN == 128) ? 64 : 32);

    extern __shared__ float smem[];
    const uint32_t s0 = (uint32_t)__cvta_generic_to_shared(smem);

    const int T = K >> 5;

    // ldmatrix lane-address offsets (floats) within A / B tile bases
    const uint32_t aoff = (uint32_t)((moff + (lane & 15)) * 36 + (lane >> 4) * 4);
    const uint32_t boff = (uint32_t)((wn * 32 + ((lane >> 4) << 3) + (lane & 7)) * 36
                                     + ((lane >> 3) & 1) * 4);

    float acc[MI][4][4];
    #pragma unroll
    for (int mi = 0; mi < MI; mi++)
        #pragma unroll
        for (int ni = 0; ni < 4; ni++)
            #pragma unroll
            for (int e = 0; e < 4; e++) acc[mi][ni][e] = 0.0f;

    auto load_tile = [&](int t, int st) {
        const int k0 = t * 32;
        const uint32_t au = s0 + (uint32_t)(st * BUFSZ) * 4u;
        const uint32_t bu = au + 4608u * 4u;
        #pragma unroll
        for (int i = 0; i < 4; i++) {
            int f = tid + i * 256;
            int row = f >> 3, c = f & 7;
            cp16(au + (uint32_t)(row * 36 + c * 4) * 4u,
                 A + (long)(bm + row) * lda + k0 + c * 4);
        }
        #pragma unroll
        for (int i = 0; i < BITERS; i++) {
            int f = tid + i * 256;
            int row = f >> 3, c = f & 7;
            cp16(bu + (uint32_t)(row * 36 + c * 4) * 4u,
                 B + (long)(bn + row) * ldb + k0 + c * 4);
        }
        CP_COMMIT();
    };

    auto compute = [&](int st) {
        const uint32_t au = s0 + (uint32_t)(st * BUFSZ) * 4u + aoff * 4u;
        const uint32_t bu = s0 + (uint32_t)(st * BUFSZ + 4608) * 4u + boff * 4u;
        #pragma unroll
        for (int ks = 0; ks < 4; ks++) {
            const uint32_t kb = (uint32_t)(ks * 8) * 4u;
            uint32_t af[MI][4];
            #pragma unroll
            for (int mi = 0; mi < MI; mi++)
                LDSM_X4(af[mi], au + (uint32_t)(mi * 16 * 36) * 4u + kb);
            uint32_t bf[2][4];
            #pragma unroll
            for (int p = 0; p < 2; p++)
                LDSM_X4(bf[p], bu + (uint32_t)(p * 16 * 36) * 4u + kb);
            #pragma unroll
            for (int mi = 0; mi < MI; mi++) {
                #pragma unroll
                for (int ni = 0; ni < 4; ni++) {
                    const uint32_t* bp = bf[ni >> 1];
                    MMA_TF32(acc[mi][ni],
                             af[mi][0], af[mi][1], af[mi][2], af[mi][3],
                             bp[(ni & 1) * 2], bp[(ni & 1) * 2 + 1]);
                }
            }
        }
    };

    load_tile(0, 0);
    if (T > 1) load_tile(1, 1);
    int st = 0;
    for (int t = 0; t < T; t++) {
        if (t + 1 < T) { CP_WAIT1(); } else { CP_WAIT0(); }
        __syncthreads();
        if (t + 2 < T) {
            int ns = st + 2; if (ns >= 3) ns -= 3;
            load_tile(t + 2, ns);
        }
        compute(st);
        if (++st == 3) st = 0;
    }

    #pragma unroll
    for (int mi = 0; mi < MI; mi++) {
        int r0 = bm + moff + mi * 16 + g;
        #pragma unroll
        for (int ni = 0; ni < 4; ni++) {
            int c0 = bn + wn * 32 + ni * 8 + 2 * tg;
            float e0 = acc[mi][ni][0], e1 = acc[mi][ni][1];
            float e2 = acc[mi][ni][2], e3 = acc[mi][ni][3];
            if (RELU) {
                e0 = fmaxf(e0, 0.f); e1 = fmaxf(e1, 0.f);
                e2 = fmaxf(e2, 0.f); e3 = fmaxf(e3, 0.f);
            }
            if (ROUNDC) {
                e0 = roundtf(e0); e1 = roundtf(e1);
                e2 = roundtf(e2); e3 = roundtf(e3);
            }
            *reinterpret_cast<float2*>(C + (long)r0 * ldc + c0) =
                make_float2(e0, e1);
            *reinterpret_cast<float2*>(C + (long)(r0 + 8) * ldc + c0) =
                make_float2(e2, e3);
        }
    }
}

template<int TILEN, int RELU, int ROUNDC>
__global__ __launch_bounds__(256, 2)
void mgemm_k(const float* __restrict__ A, const float* __restrict__ B,
             float* __restrict__ C, int K, int lda, int ldb, int ldc)
{
    gemm_body<TILEN, RELU, ROUNDC>(
        A, B, C, K, lda, ldb, ldc, blockIdx.y * 128, blockIdx.x * TILEN);
}

__global__ __launch_bounds__(256, 2)
void qkv_k(const float* __restrict__ A,
           const float* __restrict__ Bq, const float* __restrict__ Bk,
           const float* __restrict__ Bv,
           float* __restrict__ Cq, float* __restrict__ Ck,
           float* __restrict__ Cv)
{
    const int mat = blockIdx.x >> 3;
    const int bn = (blockIdx.x & 7) * 128;
    const int bm = blockIdx.y * 128;
    const float* B = (mat == 0) ? Bq : (mat == 1) ? Bk : Bv;
    float*       C = (mat == 0) ? Cq : (mat == 1) ? Ck : Cv;
    gemm_body<128, 0, 1>(A, B, C, FF, FF, FF, HDALL, bm, bn);
}

// ================= fused flash attention (ldmatrix fragments) ================
#define FL_Q   0
#define FL_K   8448
#define FL_V   25344
#define FL_P   42240
#define FL_RM  46592
#define FL_RS  46848
#define FL_SM  (47104 * 4)

__global__ __launch_bounds__(256, 1)
void flash_k(const float* __restrict__ q, const float* __restrict__ k,
             const float* __restrict__ v, float* __restrict__ o)
{
    const int head = blockIdx.y;
    const int pair = blockIdx.x;
    const int tid = threadIdx.x;
    const int wid = tid >> 5, lane = tid & 31;
    const int g = lane >> 2, tg = lane & 3;
    const int wm = wid >> 2, wn = wid & 3;

    extern __shared__ float sm[];
    const uint32_t su = (uint32_t)__cvta_generic_to_shared(sm);

    const float* qh = q + head * HD;
    const float* kh = k + head * HD;
    const float* vh = v + head * HD;

    // ldmatrix lane offsets (floats)
    const uint32_t qoff = (uint32_t)((wm * 32 + (lane & 15)) * 132 + (lane >> 4) * 4);
    const uint32_t koff = (uint32_t)((wn * 16 + ((lane >> 4) << 3) + (lane & 7)) * 132
                                     + ((lane >> 3) & 1) * 4);
    const uint32_t poff = (uint32_t)((wm * 32 + (lane & 15)) * 68 + (lane >> 4) * 4);

    for (int half = 0; half < 2; half++) {
        const int j  = half ? (31 - pair) : pair;
        const int r0 = j * 64;
        const int ntiles = j + 1;

        #pragma unroll
        for (int i = 0; i < 8; i++) {
            int f = tid + i * 256;
            int row = f >> 5, c = f & 31;
            cp16(su + (uint32_t)(FL_Q + row * 132 + c * 4) * 4u,
                 qh + (long)(r0 + row) * HDALL + c * 4);
        }
        {
            #pragma unroll
            for (int i = 0; i < 8; i++) {
                int f = tid + i * 256;
                int row = f >> 5, c = f & 31;
                cp16(su + (uint32_t)(FL_K + row * 132 + c * 4) * 4u,
                     kh + (long)row * HDALL + c * 4);
                cp16(su + (uint32_t)(FL_V + row * 132 + c * 4) * 4u,
                     vh + (long)row * HDALL + c * 4);
            }
            CP_COMMIT();
        }

        float oacc[2][4][4];
        #pragma unroll
        for (int mi = 0; mi < 2; mi++)
            #pragma unroll
            for (int ni = 0; ni < 4; ni++)
                #pragma unroll
                for (int e = 0; e < 4; e++) oacc[mi][ni][e] = 0.0f;
        float mrow[2][2], lrow[2][2];
        #pragma unroll
        for (int mi = 0; mi < 2; mi++) {
            mrow[mi][0] = -3.0e38f; mrow[mi][1] = -3.0e38f;
            lrow[mi][0] = 0.0f;     lrow[mi][1] = 0.0f;
        }

        for (int t = 0; t < ntiles; t++) {
            const int buf = t & 1;
            CP_WAIT0();
            __syncthreads();
            if (t + 1 < ntiles) {
                const int nb = (t + 1) & 1;
                const long kv0 = (long)(t + 1) * 64;
                #pragma unroll
                for (int i = 0; i < 8; i++) {
                    int f = tid + i * 256;
                    int row = f >> 5, c = f & 31;
                    cp16(su + (uint32_t)(FL_K + nb * 8448 + row * 132 + c * 4) * 4u,
                         kh + (kv0 + row) * HDALL + c * 4);
                    cp16(su + (uint32_t)(FL_V + nb * 8448 + row * 132 + c * 4) * 4u,
                         vh + (kv0 + row) * HDALL + c * 4);
                }
                CP_COMMIT();
            }

            const float* Vs = sm + FL_V + buf * 8448;
            const uint32_t qa = su + (uint32_t)FL_Q * 4u + qoff * 4u;
            const uint32_t ka = su + (uint32_t)(FL_K + buf * 8448) * 4u + koff * 4u;

            // ---- QK^T
            float sacc[2][2][4];
            #pragma unroll
            for (int mi = 0; mi < 2; mi++)
                #pragma unroll
                for (int ni = 0; ni < 2; ni++)
                    #pragma unroll
                    for (int e = 0; e < 4; e++) sacc[mi][ni][e] = 0.0f;
            #pragma unroll
            for (int kc = 0; kc < 16; kc++) {
                const uint32_t kb = (uint32_t)(kc * 8) * 4u;
                uint32_t af[2][4], bf[4];
                LDSM_X4(af[0], qa + kb);
                LDSM_X4(af[1], qa + (uint32_t)(16 * 132) * 4u + kb);
                LDSM_X4(bf, ka + kb);
                #pragma unroll
                for (int mi = 0; mi < 2; mi++) {
                    MMA_TF32(sacc[mi][0], af[mi][0], af[mi][1], af[mi][2], af[mi][3],
                             bf[0], bf[1]);
                    MMA_TF32(sacc[mi][1], af[mi][0], af[mi][1], af[mi][2], af[mi][3],
                             bf[2], bf[3]);
                }
            }

            if (t == ntiles - 1) {
                #pragma unroll
                for (int mi = 0; mi < 2; mi++) {
                    int ra = wm * 32 + mi * 16 + g;
                    #pragma unroll
                    for (int ni = 0; ni < 2; ni++) {
                        int c0 = wn * 16 + ni * 8 + 2 * tg;
                        if (c0     > ra)     sacc[mi][ni][0] = -3.0e38f;
                        if (c0 + 1 > ra)     sacc[mi][ni][1] = -3.0e38f;
                        if (c0     > ra + 8) sacc[mi][ni][2] = -3.0e38f;
                        if (c0 + 1 > ra + 8) sacc[mi][ni][3] = -3.0e38f;
                    }
                }
            }

            // ---- row max
            #pragma unroll
            for (int mi = 0; mi < 2; mi++) {
                float pa = fmaxf(fmaxf(sacc[mi][0][0], sacc[mi][0][1]),
                                 fmaxf(sacc[mi][1][0], sacc[mi][1][1]));
                float pb = fmaxf(fmaxf(sacc[mi][0][2], sacc[mi][0][3]),
                                 fmaxf(sacc[mi][1][2], sacc[mi][1][3]));
                pa = fmaxf(pa, __shfl_xor_sync(0xffffffffu, pa, 1));
                pa = fmaxf(pa, __shfl_xor_sync(0xffffffffu, pa, 2));
                pb = fmaxf(pb, __shfl_xor_sync(0xffffffffu, pb, 1));
                pb = fmaxf(pb, __shfl_xor_sync(0xffffffffu, pb, 2));
                if (tg == 0) {
                    int ra = wm * 32 + mi * 16 + g;
                    sm[FL_RM + ra * 4 + wn]       = pa;
                    sm[FL_RM + (ra + 8) * 4 + wn] = pb;
                }
            }
            __syncthreads();

            float scal[2][2], mnew[2][2];
            #pragma unroll
            for (int mi = 0; mi < 2; mi++) {
                #pragma unroll
                for (int h2 = 0; h2 < 2; h2++) {
                    int r = wm * 32 + mi * 16 + g + h2 * 8;
                    float rm = fmaxf(fmaxf(sm[FL_RM + r * 4 + 0], sm[FL_RM + r * 4 + 1]),
                                     fmaxf(sm[FL_RM + r * 4 + 2], sm[FL_RM + r * 4 + 3]));
                    float mn = fmaxf(mrow[mi][h2], rm);
                    scal[mi][h2] = fexp(mrow[mi][h2] - mn);
                    mnew[mi][h2] = mn;
                }
            }
            float psum[2][2] = {{0.f, 0.f}, {0.f, 0.f}};
            #pragma unroll
            for (int mi = 0; mi < 2; mi++) {
                int ra = wm * 32 + mi * 16 + g;
                #pragma unroll
                for (int ni = 0; ni < 2; ni++) {
                    int c0 = wn * 16 + ni * 8 + 2 * tg;
                    float p0 = fexp(sacc[mi][ni][0] - mnew[mi][0]);
                    float p1 = fexp(sacc[mi][ni][1] - mnew[mi][0]);
                    float p2 = fexp(sacc[mi][ni][2] - mnew[mi][1]);
                    float p3 = fexp(sacc[mi][ni][3] - mnew[mi][1]);
                    psum[mi][0] += p0 + p1;
                    psum[mi][1] += p2 + p3;
                    *reinterpret_cast<float2*>(sm + FL_P + ra * 68 + c0) =
                        make_float2(roundtf(p0), roundtf(p1));
                    *reinterpret_cast<float2*>(sm + FL_P + (ra + 8) * 68 + c0) =
                        make_float2(roundtf(p2), roundtf(p3));
                }
            }
            #pragma unroll
            for (int mi = 0; mi < 2; mi++) {
                float sa = psum[mi][0], sb = psum[mi][1];
                sa += __shfl_xor_sync(0xffffffffu, sa, 1);
                sa += __shfl_xor_sync(0xffffffffu, sa, 2);
                sb += __shfl_xor_sync(0xffffffffu, sb, 1);
                sb += __shfl_xor_sync(0xffffffffu, sb, 2);
                if (tg == 0) {
                    int ra = wm * 32 + mi * 16 + g;
                    sm[FL_RS + ra * 4 + wn]       = sa;
                    sm[FL_RS + (ra + 8) * 4 + wn] = sb;
                }
            }
            __syncthreads();

            #pragma unroll
            for (int mi = 0; mi < 2; mi++) {
                #pragma unroll
                for (int h2 = 0; h2 < 2; h2++) {
                    int r = wm * 32 + mi * 16 + g + h2 * 8;
                    float rs = sm[FL_RS + r * 4 + 0] + sm[FL_RS + r * 4 + 1]
                             + sm[FL_RS + r * 4 + 2] + sm[FL_RS + r * 4 + 3];
                    lrow[mi][h2] = lrow[mi][h2] * scal[mi][h2] + rs;
                    mrow[mi][h2] = mnew[mi][h2];
                }
                #pragma unroll
                for (int ni = 0; ni < 4; ni++) {
                    oacc[mi][ni][0] *= scal[mi][0];
                    oacc[mi][ni][1] *= scal[mi][0];
                    oacc[mi][ni][2] *= scal[mi][1];
                    oacc[mi][ni][3] *= scal[mi][1];
                }
            }

            // ---- PV
            const uint32_t pa2 = su + (uint32_t)FL_P * 4u + poff * 4u;
            #pragma unroll
            for (int kc = 0; kc < 8; kc++) {
                const int kk = kc * 8;
                const uint32_t kb = (uint32_t)kk * 4u;
                uint32_t af[2][4];
                LDSM_X4(af[0], pa2 + kb);
                LDSM_X4(af[1], pa2 + (uint32_t)(16 * 68) * 4u + kb);
                uint32_t bf[4][2];
                #pragma unroll
                for (int ni = 0; ni < 4; ni++) {
                    int n = wn * 32 + ni * 8 + g;
                    bf[ni][0] = __float_as_uint(Vs[(kk + tg) * 132 + n]);
                    bf[ni][1] = __float_as_uint(Vs[(kk + tg + 4) * 132 + n]);
                }
                #pragma unroll
                for (int mi = 0; mi < 2; mi++)
                    #pragma unroll
                    for (int ni = 0; ni < 4; ni++)
                        MMA_TF32(oacc[mi][ni],
                                 af[mi][0], af[mi][1], af[mi][2], af[mi][3],
                                 bf[ni][0], bf[ni][1]);
            }
        }

        #pragma unroll
        for (int mi = 0; mi < 2; mi++) {
            float ia = 1.0f / lrow[mi][0];
            float ib = 1.0f / lrow[mi][1];
            int ra = r0 + wm * 32 + mi * 16 + g;
            #pragma unroll
            for (int ni = 0; ni < 4; ni++) {
                int c0 = head * HD + wn * 32 + ni * 8 + 2 * tg;
                *reinterpret_cast<float2*>(o + (long)ra * HDALL + c0) =
                    make_float2(roundtf(oacc[mi][ni][0] * ia),
                                roundtf(oacc[mi][ni][1] * ia));
                *reinterpret_cast<float2*>(o + (long)(ra + 8) * HDALL + c0) =
                    make_float2(roundtf(oacc[mi][ni][2] * ib),
                                roundtf(oacc[mi][ni][3] * ib));
            }
        }
        __syncthreads();
    }
}

// ---------------- launch -----------------------------------------------------
#define SM128 110592
#define SM64   82944

extern "C" void kernel_launch(void* const* d_in, const int* in_sizes, int n_in,
                              void* d_out, int out_size)
{
    const int*   x    = (const int*)  d_in[0];
    const float* emb  = (const float*)d_in[1];
    const float* ff_w = (const float*)d_in[2];
    const float* q_w  = (const float*)d_in[3];
    const float* k_w  = (const float*)d_in[4];
    const float* v_w  = (const float*)d_in[5];
    const float* o_w  = (const float*)d_in[6];
    float* out = (float*)d_out;

    float *h, *hf, *q, *k, *v, *o;
    float *wff, *wq, *wk, *wv, *wo, *embr;
    cudaGetSymbolAddress((void**)&h,  g_h);
    cudaGetSymbolAddress((void**)&hf, g_hf);
    cudaGetSymbolAddress((void**)&q,  g_q);
    cudaGetSymbolAddress((void**)&k,  g_k);
    cudaGetSymbolAddress((void**)&v,  g_v);
    cudaGetSymbolAddress((void**)&o,  g_o);
    cudaGetSymbolAddress((void**)&wff, g_wff);
    cudaGetSymbolAddress((void**)&wq,  g_wq);
    cudaGetSymbolAddress((void**)&wk,  g_wk);
    cudaGetSymbolAddress((void**)&wv,  g_wv);
    cudaGetSymbolAddress((void**)&wo,  g_wo);
    cudaGetSymbolAddress((void**)&embr, g_embr);

    cudaFuncSetAttribute(mgemm_k<128,1,1>, cudaFuncAttributeMaxDynamicSharedMemorySize, SM128);
    cudaFuncSetAttribute(mgemm_k<128,0,0>, cudaFuncAttributeMaxDynamicSharedMemorySize, SM128);
    cudaFuncSetAttribute(mgemm_k<64,0,1>,  cudaFuncAttributeMaxDynamicSharedMemorySize, SM64);
    cudaFuncSetAttribute(qkv_k,            cudaFuncAttributeMaxDynamicSharedMemorySize, SM128);
    cudaFuncSetAttribute(flash_k,          cudaFuncAttributeMaxDynamicSharedMemorySize, FL_SM);

    // ---- prep: transpose + round weights, round emb
    dim3 trb(32, 8);
    for (int l = 0; l < NL; l++) {
        trn_k<<<dim3(FF/32, EM/32), trb>>>(ff_w + (long)l * EM * FF,
                                           wff + (long)l * FF * EM, EM, FF);
        trn_k<<<dim3(HDALL/32, FF/32), trb>>>(q_w + (long)l * FF * HDALL,
                                              wq + (long)l * HDALL * FF, FF, HDALL);
        trn_k<<<dim3(HDALL/32, FF/32), trb>>>(k_w + (long)l * FF * HDALL,
                                              wk + (long)l * HDALL * FF, FF, HDALL);
        trn_k<<<dim3(HDALL/32, FF/32), trb>>>(v_w + (long)l * FF * HDALL,
                                              wv + (long)l * HDALL * FF, FF, HDALL);
        trn_k<<<dim3(EM/32, HDALL/32), trb>>>(o_w + (long)l * HDALL * EM,
                                              wo + (long)l * EM * HDALL, HDALL, EM);
    }
    rnd_k<<<(int)((long)VC * EM / 1024), 256>>>(emb, embr);

    embed_k<<<SQ, 256>>>(x, emb, h);

    for (int l = 0; l < NL; l++) {
        // hf = relu(h @ ff_w[l])  (B = wff [F][E], ldb = EM)
        mgemm_k<128,1,1><<<dim3(FF/128, SQ/128, 1), 256, SM128>>>(
            h, wff + (long)l * FF * EM, hf, EM, EM, EM, FF);

        // q,k,v fused (B = [HD_ALL][F], ldb = FF)
        qkv_k<<<dim3(3 * HDALL / 128, SQ/128, 1), 256, SM128>>>(
            hf,
            wq + (long)l * HDALL * FF,
            wk + (long)l * HDALL * FF,
            wv + (long)l * HDALL * FF,
            q, k, v);

        // fused causal attention
        flash_k<<<dim3(16, NH, 1), 256, FL_SM>>>(q, k, v, o);

        // h = o @ o_w[l]  (B = wo [E][HD_ALL], ldb = HDALL)
        mgemm_k<64,0,1><<<dim3(EM/64, SQ/128, 1), 256, SM64>>>(
            o, wo + (long)l * EM * HDALL, h, HDALL, HDALL, HDALL, EM);
    }

    // logits = h @ emb^T  (B = embr [V][E], ldb = EM)
    mgemm_k<128,0,0><<<dim3(VC/128, SQ/128, 1), 256, SM128>>>(
        h, embr, out, EM, EM, EM, VC);
}

// round 17
// speedup vs baseline: 4.3524x; 1.0105x over previous
#include <cuda_runtime.h>
#include <cuda_bf16.h>
#include <math.h>
#include <stdint.h>

#define SQ   2048
#define EM   1024
#define FF   4096
#define NH   8
#define HD   128
#define NL   4
#define VC   32000
#define HDALL (NH * HD)

// ---------------- scratch (device globals) ----------------------------------
__device__ float g_h [SQ * EM];
__device__ float g_hf[SQ * FF];
__device__ float g_q [SQ * HDALL];
__device__ float g_k [SQ * HDALL];
__device__ float g_v [SQ * HDALL];
__device__ float g_o [SQ * HDALL];
// transposed + tf32-rounded weights
__device__ float g_wff[NL * FF * EM];        // [F][E]
__device__ float g_wq [NL * HDALL * FF];     // [HD_ALL][F]
__device__ float g_wk [NL * HDALL * FF];
__device__ float g_wv [NL * HDALL * FF];
__device__ float g_wo [NL * EM * HDALL];     // [E][HD_ALL]
__device__ float g_embr[(size_t)VC * EM];    // rounded [V][E]

// ---------------- helpers ----------------------------------------------------
__device__ __forceinline__ uint32_t f2tf(float f) {
    uint32_t r;
    asm("cvt.rna.tf32.f32 %0, %1;" : "=r"(r) : "f"(f));
    return r;
}
__device__ __forceinline__ float roundtf(float f) {
    return __uint_as_float(f2tf(f));
}
__device__ __forceinline__ void cp16(uint32_t dst, const float* src) {
    asm volatile("cp.async.cg.shared.global [%0], [%1], 16;"
                 :: "r"(dst), "l"(src) : "memory");
}
#define CP_COMMIT() asm volatile("cp.async.commit_group;" ::: "memory")
#define CP_WAIT0()  asm volatile("cp.async.wait_group 0;" ::: "memory")
#define CP_WAIT1()  asm volatile("cp.async.wait_group 1;" ::: "memory")

#define MMA_TF32(d, a0, a1, a2, a3, b0, b1) \
    asm volatile("mma.sync.aligned.m16n8k8.row.col.f32.tf32.tf32.f32 " \
                 "{%0,%1,%2,%3},{%4,%5,%6,%7},{%8,%9},{%0,%1,%2,%3};" \
                 : "+f"((d)[0]), "+f"((d)[1]), "+f"((d)[2]), "+f"((d)[3]) \
                 : "r"(a0), "r"(a1), "r"(a2), "r"(a3), "r"(b0), "r"(b1))

#define LDSM_X4(r, a) \
    asm volatile("ldmatrix.sync.aligned.m8n8.x4.shared.b16 {%0,%1,%2,%3}, [%4];" \
                 : "=r"((r)[0]), "=r"((r)[1]), "=r"((r)[2]), "=r"((r)[3]) \
                 : "r"(a))

// exp(x), x <= 0, FMA-pipe 2^f (deg 6, rel err ~1e-5)
__device__ __forceinline__ float fexp(float x) {
    float y = fmaxf(x * 1.4426950408889634f, -127.0f);
    float n = floorf(y);
    float f = y - n;
    float p = 0.00015403530393f;
    p = fmaf(p, f, 0.0013333558146f);
    p = fmaf(p, f, 0.0096181291076f);
    p = fmaf(p, f, 0.0555041086648f);
    p = fmaf(p, f, 0.2402265069591f);
    p = fmaf(p, f, 0.6931471805599f);
    p = fmaf(p, f, 1.0f);
    return p * __int_as_float(((int)n + 127) << 23);
}

// ---------------- prep: batched transpose+round ------------------------------
// src [z][R][C] -> dst [z][C][R], tf32-rounded. grid (C/32, R/32, NL)
__global__ void trn_k(const float* __restrict__ src, float* __restrict__ dst,
                      int R, int C)
{
    __shared__ float t[32][33];
    const long zs = (long)blockIdx.z * R * C;
    const int r0 = blockIdx.y * 32, c0 = blockIdx.x * 32;
    const int tx = threadIdx.x, ty = threadIdx.y;
    #pragma unroll
    for (int i = 0; i < 4; i++)
        t[ty + 8 * i][tx] = roundtf(src[zs + (long)(r0 + ty + 8 * i) * C + c0 + tx]);
    __syncthreads();
    #pragma unroll
    for (int i = 0; i < 4; i++)
        dst[zs + (long)(c0 + ty + 8 * i) * R + r0 + tx] = t[tx][ty + 8 * i];
}

__global__ void rnd_k(const float* __restrict__ src, float* __restrict__ dst)
{
    long i = ((long)blockIdx.x * 256 + threadIdx.x);
    float4 v = reinterpret_cast<const float4*>(src)[i];
    v.x = roundtf(v.x); v.y = roundtf(v.y);
    v.z = roundtf(v.z); v.w = roundtf(v.w);
    reinterpret_cast<float4*>(dst)[i] = v;
}

// ---------------- embedding gather (rounds to tf32) --------------------------
__global__ void embed_k(const int* __restrict__ x, const float* __restrict__ emb,
                        float* __restrict__ h)
{
    int s = blockIdx.x;
    int id = x[s];
    float4 v = reinterpret_cast<const float4*>(emb + (long)id * EM)[threadIdx.x];
    v.x = roundtf(v.x); v.y = roundtf(v.y);
    v.z = roundtf(v.z); v.w = roundtf(v.w);
    reinterpret_cast<float4*>(h + (long)s * EM)[threadIdx.x] = v;
}

// ---------------- GEMM body: 128 x TILEN, BK=32, 3-stage, ldmatrix ----------
// A [M][K] k-contig, B [N][K] k-contig, both pre-rounded to tf32.
template<int TILEN, int RELU, int ROUNDC>
__device__ __forceinline__
void gemm_body(const float* __restrict__ A, const float* __restrict__ B,
               float* __restrict__ C, int K, int lda, int ldb, int ldc,
               int bm, int bn)
{
    constexpr int MI     = (TILEN == 128) ? 4 : 2;
    constexpr int BBUF   = (TILEN == 128) ? 4608 : 2304;
    constexpr int BUFSZ  = 4608 + BBUF;
    constexpr int BITERS = (TILEN == 128) ? 4 : 2;

    const int tid = threadIdx.x;
    const int wid = tid >> 5, lane = tid & 31;
    const int g = lane >> 2, tg = lane & 3;
    const int wm = (TILEN == 128) ? (wid >> 2) : (wid >> 1);
    const int wn = (TILEN == 128) ? (wid & 3)  : (wid & 1);
    const int moff = wm * ((TILEN == 128) ? 64 : 32);

    extern __shared__ float smem[];
    const uint32_t s0 = (uint32_t)__cvta_generic_to_shared(smem);

    const int T = K >> 5;

    const uint32_t aoff = (uint32_t)((moff + (lane & 15)) * 36 + (lane >> 4) * 4);
    const uint32_t boff = (uint32_t)((wn * 32 + ((lane >> 4) << 3) + (lane & 7)) * 36
                                     + ((lane >> 3) & 1) * 4);

    float acc[MI][4][4];
    #pragma unroll
    for (int mi = 0; mi < MI; mi++)
        #pragma unroll
        for (int ni = 0; ni < 4; ni++)
            #pragma unroll
            for (int e = 0; e < 4; e++) acc[mi][ni][e] = 0.0f;

    auto load_tile = [&](int t, int st) {
        const int k0 = t * 32;
        const uint32_t au = s0 + (uint32_t)(st * BUFSZ) * 4u;
        const uint32_t bu = au + 4608u * 4u;
        #pragma unroll
        for (int i = 0; i < 4; i++) {
            int f = tid + i * 256;
            int row = f >> 3, c = f & 7;
            cp16(au + (uint32_t)(row * 36 + c * 4) * 4u,
                 A + (long)(bm + row) * lda + k0 + c * 4);
        }
        #pragma unroll
        for (int i = 0; i < BITERS; i++) {
            int f = tid + i * 256;
            int row = f >> 3, c = f & 7;
            cp16(bu + (uint32_t)(row * 36 + c * 4) * 4u,
                 B + (long)(bn + row) * ldb + k0 + c * 4);
        }
        CP_COMMIT();
    };

    auto compute = [&](int st) {
        const uint32_t au = s0 + (uint32_t)(st * BUFSZ) * 4u + aoff * 4u;
        const uint32_t bu = s0 + (uint32_t)(st * BUFSZ + 4608) * 4u + boff * 4u;
        #pragma unroll
        for (int ks = 0; ks < 4; ks++) {
            const uint32_t kb = (uint32_t)(ks * 8) * 4u;
            uint32_t af[MI][4];
            #pragma unroll
            for (int mi = 0; mi < MI; mi++)
                LDSM_X4(af[mi], au + (uint32_t)(mi * 16 * 36) * 4u + kb);
            uint32_t bf[2][4];
            #pragma unroll
            for (int p = 0; p < 2; p++)
                LDSM_X4(bf[p], bu + (uint32_t)(p * 16 * 36) * 4u + kb);
            #pragma unroll
            for (int mi = 0; mi < MI; mi++) {
                #pragma unroll
                for (int ni = 0; ni < 4; ni++) {
                    const uint32_t* bp = bf[ni >> 1];
                    MMA_TF32(acc[mi][ni],
                             af[mi][0], af[mi][1], af[mi][2], af[mi][3],
                             bp[(ni & 1) * 2], bp[(ni & 1) * 2 + 1]);
                }
            }
        }
    };

    load_tile(0, 0);
    if (T > 1) load_tile(1, 1);
    int st = 0;
    for (int t = 0; t < T; t++) {
        if (t + 1 < T) { CP_WAIT1(); } else { CP_WAIT0(); }
        __syncthreads();
        if (t + 2 < T) {
            int ns = st + 2; if (ns >= 3) ns -= 3;
            load_tile(t + 2, ns);
        }
        compute(st);
        if (++st == 3) st = 0;
    }

    #pragma unroll
    for (int mi = 0; mi < MI; mi++) {
        int r0 = bm + moff + mi * 16 + g;
        #pragma unroll
        for (int ni = 0; ni < 4; ni++) {
            int c0 = bn + wn * 32 + ni * 8 + 2 * tg;
            float e0 = acc[mi][ni][0], e1 = acc[mi][ni][1];
            float e2 = acc[mi][ni][2], e3 = acc[mi][ni][3];
            if (RELU) {
                e0 = fmaxf(e0, 0.f); e1 = fmaxf(e1, 0.f);
                e2 = fmaxf(e2, 0.f); e3 = fmaxf(e3, 0.f);
            }
            if (ROUNDC) {
                e0 = roundtf(e0); e1 = roundtf(e1);
                e2 = roundtf(e2); e3 = roundtf(e3);
            }
            *reinterpret_cast<float2*>(C + (long)r0 * ldc + c0) =
                make_float2(e0, e1);
            *reinterpret_cast<float2*>(C + (long)(r0 + 8) * ldc + c0) =
                make_float2(e2, e3);
        }
    }
}

template<int TILEN, int RELU, int ROUNDC>
__global__ __launch_bounds__(256, 2)
void mgemm_k(const float* __restrict__ A, const float* __restrict__ B,
             float* __restrict__ C, int K, int lda, int ldb, int ldc)
{
    gemm_body<TILEN, RELU, ROUNDC>(
        A, B, C, K, lda, ldb, ldc, blockIdx.y * 128, blockIdx.x * TILEN);
}

// grid.x = m-blocks (fast), grid.y = n-blocks: wave-local L2 reuse of B
__global__ __launch_bounds__(256, 2)
void mgemm_mx_k(const float* __restrict__ A, const float* __restrict__ B,
                float* __restrict__ C, int K, int lda, int ldb, int ldc)
{
    gemm_body<128, 0, 0>(
        A, B, C, K, lda, ldb, ldc, blockIdx.x * 128, blockIdx.y * 128);
}

__global__ __launch_bounds__(256, 2)
void qkv_k(const float* __restrict__ A,
           const float* __restrict__ Bq, const float* __restrict__ Bk,
           const float* __restrict__ Bv,
           float* __restrict__ Cq, float* __restrict__ Ck,
           float* __restrict__ Cv)
{
    const int mat = blockIdx.x >> 3;
    const int bn = (blockIdx.x & 7) * 128;
    const int bm = blockIdx.y * 128;
    const float* B = (mat == 0) ? Bq : (mat == 1) ? Bk : Bv;
    float*       C = (mat == 0) ? Cq : (mat == 1) ? Ck : Cv;
    gemm_body<128, 0, 1>(A, B, C, FF, FF, FF, HDALL, bm, bn);
}

// ================= fused flash attention (ldmatrix fragments) ================
#define FL_Q   0
#define FL_K   8448
#define FL_V   25344
#define FL_P   42240
#define FL_RM  46592
#define FL_RS  46848
#define FL_SM  (47104 * 4)

__global__ __launch_bounds__(256, 1)
void flash_k(const float* __restrict__ q, const float* __restrict__ k,
             const float* __restrict__ v, float* __restrict__ o)
{
    const int head = blockIdx.y;
    const int pair = blockIdx.x;
    const int tid = threadIdx.x;
    const int wid = tid >> 5, lane = tid & 31;
    const int g = lane >> 2, tg = lane & 3;
    const int wm = wid >> 2, wn = wid & 3;

    extern __shared__ float sm[];
    const uint32_t su = (uint32_t)__cvta_generic_to_shared(sm);

    const float* qh = q + head * HD;
    const float* kh = k + head * HD;
    const float* vh = v + head * HD;

    const uint32_t qoff = (uint32_t)((wm * 32 + (lane & 15)) * 132 + (lane >> 4) * 4);
    const uint32_t koff = (uint32_t)((wn * 16 + ((lane >> 4) << 3) + (lane & 7)) * 132
                                     + ((lane >> 3) & 1) * 4);
    const uint32_t poff = (uint32_t)((wm * 32 + (lane & 15)) * 68 + (lane >> 4) * 4);

    for (int half = 0; half < 2; half++) {
        const int j  = half ? (31 - pair) : pair;
        const int r0 = j * 64;
        const int ntiles = j + 1;

        #pragma unroll
        for (int i = 0; i < 8; i++) {
            int f = tid + i * 256;
            int row = f >> 5, c = f & 31;
            cp16(su + (uint32_t)(FL_Q + row * 132 + c * 4) * 4u,
                 qh + (long)(r0 + row) * HDALL + c * 4);
        }
        {
            #pragma unroll
            for (int i = 0; i < 8; i++) {
                int f = tid + i * 256;
                int row = f >> 5, c = f & 31;
                cp16(su + (uint32_t)(FL_K + row * 132 + c * 4) * 4u,
                     kh + (long)row * HDALL + c * 4);
                cp16(su + (uint32_t)(FL_V + row * 132 + c * 4) * 4u,
                     vh + (long)row * HDALL + c * 4);
            }
            CP_COMMIT();
        }

        float oacc[2][4][4];
        #pragma unroll
        for (int mi = 0; mi < 2; mi++)
            #pragma unroll
            for (int ni = 0; ni < 4; ni++)
                #pragma unroll
                for (int e = 0; e < 4; e++) oacc[mi][ni][e] = 0.0f;
        float mrow[2][2], lrow[2][2];
        #pragma unroll
        for (int mi = 0; mi < 2; mi++) {
            mrow[mi][0] = -3.0e38f; mrow[mi][1] = -3.0e38f;
            lrow[mi][0] = 0.0f;     lrow[mi][1] = 0.0f;
        }

        for (int t = 0; t < ntiles; t++) {
            const int buf = t & 1;
            CP_WAIT0();
            __syncthreads();
            if (t + 1 < ntiles) {
                const int nb = (t + 1) & 1;
                const long kv0 = (long)(t + 1) * 64;
                #pragma unroll
                for (int i = 0; i < 8; i++) {
                    int f = tid + i * 256;
                    int row = f >> 5, c = f & 31;
                    cp16(su + (uint32_t)(FL_K + nb * 8448 + row * 132 + c * 4) * 4u,
                         kh + (kv0 + row) * HDALL + c * 4);
                    cp16(su + (uint32_t)(FL_V + nb * 8448 + row * 132 + c * 4) * 4u,
                         vh + (kv0 + row) * HDALL + c * 4);
                }
                CP_COMMIT();
            }

            const float* Vs = sm + FL_V + buf * 8448;
            const uint32_t qa = su + (uint32_t)FL_Q * 4u + qoff * 4u;
            const uint32_t ka = su + (uint32_t)(FL_K + buf * 8448) * 4u + koff * 4u;

            float sacc[2][2][4];
            #pragma unroll
            for (int mi = 0; mi < 2; mi++)
                #pragma unroll
                for (int ni = 0; ni < 2; ni++)
                    #pragma unroll
                    for (int e = 0; e < 4; e++) sacc[mi][ni][e] = 0.0f;
            #pragma unroll
            for (int kc = 0; kc < 16; kc++) {
                const uint32_t kb = (uint32_t)(kc * 8) * 4u;
                uint32_t af[2][4], bf[4];
                LDSM_X4(af[0], qa + kb);
                LDSM_X4(af[1], qa + (uint32_t)(16 * 132) * 4u + kb);
                LDSM_X4(bf, ka + kb);
                #pragma unroll
                for (int mi = 0; mi < 2; mi++) {
                    MMA_TF32(sacc[mi][0], af[mi][0], af[mi][1], af[mi][2], af[mi][3],
                             bf[0], bf[1]);
                    MMA_TF32(sacc[mi][1], af[mi][0], af[mi][1], af[mi][2], af[mi][3],
                             bf[2], bf[3]);
                }
            }

            if (t == ntiles - 1) {
                #pragma unroll
                for (int mi = 0; mi < 2; mi++) {
                    int ra = wm * 32 + mi * 16 + g;
                    #pragma unroll
                    for (int ni = 0; ni < 2; ni++) {
                        int c0 = wn * 16 + ni * 8 + 2 * tg;
                        if (c0     > ra)     sacc[mi][ni][0] = -3.0e38f;
                        if (c0 + 1 > ra)     sacc[mi][ni][1] = -3.0e38f;
                        if (c0     > ra + 8) sacc[mi][ni][2] = -3.0e38f;
                        if (c0 + 1 > ra + 8) sacc[mi][ni][3] = -3.0e38f;
                    }
                }
            }

            #pragma unroll
            for (int mi = 0; mi < 2; mi++) {
                float pa = fmaxf(fmaxf(sacc[mi][0][0], sacc[mi][0][1]),
                                 fmaxf(sacc[mi][1][0], sacc[mi][1][1]));
                float pb = fmaxf(fmaxf(sacc[mi][0][2], sacc[mi][0][3]),
                                 fmaxf(sacc[mi][1][2], sacc[mi][1][3]));
                pa = fmaxf(pa, __shfl_xor_sync(0xffffffffu, pa, 1));
                pa = fmaxf(pa, __shfl_xor_sync(0xffffffffu, pa, 2));
                pb = fmaxf(pb, __shfl_xor_sync(0xffffffffu, pb, 1));
                pb = fmaxf(pb, __shfl_xor_sync(0xffffffffu, pb, 2));
                if (tg == 0) {
                    int ra = wm * 32 + mi * 16 + g;
                    sm[FL_RM + ra * 4 + wn]       = pa;
                    sm[FL_RM + (ra + 8) * 4 + wn] = pb;
                }
            }
            __syncthreads();

            float scal[2][2], mnew[2][2];
            #pragma unroll
            for (int mi = 0; mi < 2; mi++) {
                #pragma unroll
                for (int h2 = 0; h2 < 2; h2++) {
                    int r = wm * 32 + mi * 16 + g + h2 * 8;
                    float rm = fmaxf(fmaxf(sm[FL_RM + r * 4 + 0], sm[FL_RM + r * 4 + 1]),
                                     fmaxf(sm[FL_RM + r * 4 + 2], sm[FL_RM + r * 4 + 3]));
                    float mn = fmaxf(mrow[mi][h2], rm);
                    scal[mi][h2] = fexp(mrow[mi][h2] - mn);
                    mnew[mi][h2] = mn;
                }
            }
            float psum[2][2] = {{0.f, 0.f}, {0.f, 0.f}};
            #pragma unroll
            for (int mi = 0; mi < 2; mi++) {
                int ra = wm * 32 + mi * 16 + g;
                #pragma unroll
                for (int ni = 0; ni < 2; ni++) {
                    int c0 = wn * 16 + ni * 8 + 2 * tg;
                    float p0 = fexp(sacc[mi][ni][0] - mnew[mi][0]);
                    float p1 = fexp(sacc[mi][ni][1] - mnew[mi][0]);
                    float p2 = fexp(sacc[mi][ni][2] - mnew[mi][1]);
                    float p3 = fexp(sacc[mi][ni][3] - mnew[mi][1]);
                    psum[mi][0] += p0 + p1;
                    psum[mi][1] += p2 + p3;
                    *reinterpret_cast<float2*>(sm + FL_P + ra * 68 + c0) =
                        make_float2(roundtf(p0), roundtf(p1));
                    *reinterpret_cast<float2*>(sm + FL_P + (ra + 8) * 68 + c0) =
                        make_float2(roundtf(p2), roundtf(p3));
                }
            }
            #pragma unroll
            for (int mi = 0; mi < 2; mi++) {
                float sa = psum[mi][0], sb = psum[mi][1];
                sa += __shfl_xor_sync(0xffffffffu, sa, 1);
                sa += __shfl_xor_sync(0xffffffffu, sa, 2);
                sb += __shfl_xor_sync(0xffffffffu, sb, 1);
                sb += __shfl_xor_sync(0xffffffffu, sb, 2);
                if (tg == 0) {
                    int ra = wm * 32 + mi * 16 + g;
                    sm[FL_RS + ra * 4 + wn]       = sa;
                    sm[FL_RS + (ra + 8) * 4 + wn] = sb;
                }
            }
            __syncthreads();

            #pragma unroll
            for (int mi = 0; mi < 2; mi++) {
                #pragma unroll
                for (int h2 = 0; h2 < 2; h2++) {
                    int r = wm * 32 + mi * 16 + g + h2 * 8;
                    float rs = sm[FL_RS + r * 4 + 0] + sm[FL_RS + r * 4 + 1]
                             + sm[FL_RS + r * 4 + 2] + sm[FL_RS + r * 4 + 3];
                    lrow[mi][h2] = lrow[mi][h2] * scal[mi][h2] + rs;
                    mrow[mi][h2] = mnew[mi][h2];
                }
                #pragma unroll
                for (int ni = 0; ni < 4; ni++) {
                    oacc[mi][ni][0] *= scal[mi][0];
                    oacc[mi][ni][1] *= scal[mi][0];
                    oacc[mi][ni][2] *= scal[mi][1];
                    oacc[mi][ni][3] *= scal[mi][1];
                }
            }

            const uint32_t pa2 = su + (uint32_t)FL_P * 4u + poff * 4u;
            #pragma unroll
            for (int kc = 0; kc < 8; kc++) {
                const int kk = kc * 8;
                const uint32_t kb = (uint32_t)kk * 4u;
                uint32_t af[2][4];
                LDSM_X4(af[0], pa2 + kb);
                LDSM_X4(af[1], pa2 + (uint32_t)(16 * 68) * 4u + kb);
                uint32_t bf[4][2];
                #pragma unroll
                for (int ni = 0; ni < 4; ni++) {
                    int n = wn * 32 + ni * 8 + g;
                    bf[ni][0] = __float_as_uint(Vs[(kk + tg) * 132 + n]);
                    bf[ni][1] = __float_as_uint(Vs[(kk + tg + 4) * 132 + n]);
                }
                #pragma unroll
                for (int mi = 0; mi < 2; mi++)
                    #pragma unroll
                    for (int ni = 0; ni < 4; ni++)
                        MMA_TF32(oacc[mi][ni],
                                 af[mi][0], af[mi][1], af[mi][2], af[mi][3],
                                 bf[ni][0], bf[ni][1]);
            }
        }

        #pragma unroll
        for (int mi = 0; mi < 2; mi++) {
            float ia = 1.0f / lrow[mi][0];
            float ib = 1.0f / lrow[mi][1];
            int ra = r0 + wm * 32 + mi * 16 + g;
            #pragma unroll
            for (int ni = 0; ni < 4; ni++) {
                int c0 = head * HD + wn * 32 + ni * 8 + 2 * tg;
                *reinterpret_cast<float2*>(o + (long)ra * HDALL + c0) =
                    make_float2(roundtf(oacc[mi][ni][0] * ia),
                                roundtf(oacc[mi][ni][1] * ia));
                *reinterpret_cast<float2*>(o + (long)(ra + 8) * HDALL + c0) =
                    make_float2(roundtf(oacc[mi][ni][2] * ib),
                                roundtf(oacc[mi][ni][3] * ib));
            }
        }
        __syncthreads();
    }
}

// ---------------- launch -----------------------------------------------------
#define SM128 110592
#define SM64   82944

extern "C" void kernel_launch(void* const* d_in, const int* in_sizes, int n_in,
                              void* d_out, int out_size)
{
    const int*   x    = (const int*)  d_in[0];
    const float* emb  = (const float*)d_in[1];
    const float* ff_w = (const float*)d_in[2];
    const float* q_w  = (const float*)d_in[3];
    const float* k_w  = (const float*)d_in[4];
    const float* v_w  = (const float*)d_in[5];
    const float* o_w  = (const float*)d_in[6];
    float* out = (float*)d_out;

    float *h, *hf, *q, *k, *v, *o;
    float *wff, *wq, *wk, *wv, *wo, *embr;
    cudaGetSymbolAddress((void**)&h,  g_h);
    cudaGetSymbolAddress((void**)&hf, g_hf);
    cudaGetSymbolAddress((void**)&q,  g_q);
    cudaGetSymbolAddress((void**)&k,  g_k);
    cudaGetSymbolAddress((void**)&v,  g_v);
    cudaGetSymbolAddress((void**)&o,  g_o);
    cudaGetSymbolAddress((void**)&wff, g_wff);
    cudaGetSymbolAddress((void**)&wq,  g_wq);
    cudaGetSymbolAddress((void**)&wk,  g_wk);
    cudaGetSymbolAddress((void**)&wv,  g_wv);
    cudaGetSymbolAddress((void**)&wo,  g_wo);
    cudaGetSymbolAddress((void**)&embr, g_embr);

    cudaFuncSetAttribute(mgemm_k<128,1,1>, cudaFuncAttributeMaxDynamicSharedMemorySize, SM128);
    cudaFuncSetAttribute(mgemm_mx_k,       cudaFuncAttributeMaxDynamicSharedMemorySize, SM128);
    cudaFuncSetAttribute(mgemm_k<64,0,1>,  cudaFuncAttributeMaxDynamicSharedMemorySize, SM64);
    cudaFuncSetAttribute(qkv_k,            cudaFuncAttributeMaxDynamicSharedMemorySize, SM128);
    cudaFuncSetAttribute(flash_k,          cudaFuncAttributeMaxDynamicSharedMemorySize, FL_SM);

    // ---- prep: batched transpose + round (grid.z = layer)
    dim3 trb(32, 8);
    trn_k<<<dim3(FF/32, EM/32, NL), trb>>>(ff_w, wff, EM, FF);
    trn_k<<<dim3(HDALL/32, FF/32, NL), trb>>>(q_w, wq, FF, HDALL);
    trn_k<<<dim3(HDALL/32, FF/32, NL), trb>>>(k_w, wk, FF, HDALL);
    trn_k<<<dim3(HDALL/32, FF/32, NL), trb>>>(v_w, wv, FF, HDALL);
    trn_k<<<dim3(EM/32, HDALL/32, NL), trb>>>(o_w, wo, HDALL, EM);
    rnd_k<<<(int)((long)VC * EM / 1024), 256>>>(emb, embr);

    embed_k<<<SQ, 256>>>(x, emb, h);

    for (int l = 0; l < NL; l++) {
        // hf = relu(h @ ff_w[l])
        mgemm_k<128,1,1><<<dim3(FF/128, SQ/128, 1), 256, SM128>>>(
            h, wff + (long)l * FF * EM, hf, EM, EM, EM, FF);

        // q,k,v fused
        qkv_k<<<dim3(3 * HDALL / 128, SQ/128, 1), 256, SM128>>>(
            hf,
            wq + (long)l * HDALL * FF,
            wk + (long)l * HDALL * FF,
            wv + (long)l * HDALL * FF,
            q, k, v);

        // fused causal attention
        flash_k<<<dim3(16, NH, 1), 256, FL_SM>>>(q, k, v, o);

        // h = o @ o_w[l]
        mgemm_k<64,0,1><<<dim3(EM/64, SQ/128, 1), 256, SM64>>>(
            o, wo + (long)l * EM * HDALL, h, HDALL, HDALL, HDALL, EM);
    }

    // logits = h @ emb^T — grid (m=16 fast, n=250): wave-local emb reuse in L2
    mgemm_mx_k<<<dim3(SQ/128, VC/128, 1), 256, SM128>>>(
        h, embr, out, EM, EM, EM, VC);
}